// round 11
// baseline (speedup 1.0000x reference)
#include <cuda_runtime.h>
#include <cuda_bf16.h>
#include <stdint.h>
#include <math.h>

#define BB   2048
#define TT   48
#define HH   512
#define EE   256
#define VV   128
#define ENCC 1024
#define H3   1536
#define NCTA 288

// ===================== stable-ISA PTX helpers (sm_80+) ======================
__device__ __forceinline__ uint32_t smem_u32(const void* p) {
    uint32_t a;
    asm("{ .reg .u64 t; cvta.to.shared.u64 t, %1; cvt.u32.u64 %0, t; }" : "=r"(a) : "l"(p));
    return a;
}
__device__ __forceinline__ void cp_async16(uint32_t dst, const void* src) {
    asm volatile("cp.async.cg.shared.global [%0], [%1], 16;" :: "r"(dst), "l"(src));
}
#define CP_COMMIT() asm volatile("cp.async.commit_group;" ::: "memory")
#define CP_WAIT1()  asm volatile("cp.async.wait_group 1;" ::: "memory")

__device__ __forceinline__ void ldsm_x4(uint32_t* r, uint32_t addr) {
    asm volatile("ldmatrix.sync.aligned.m8n8.x4.shared.b16 {%0,%1,%2,%3}, [%4];"
                 : "=r"(r[0]), "=r"(r[1]), "=r"(r[2]), "=r"(r[3]) : "r"(addr));
}
__device__ __forceinline__ void mma16816(float* d, const uint32_t* a, const uint32_t* b) {
    asm volatile("mma.sync.aligned.m16n8k16.row.col.f32.bf16.bf16.f32 "
                 "{%0,%1,%2,%3}, {%4,%5,%6,%7}, {%8,%9}, {%0,%1,%2,%3};"
                 : "+f"(d[0]), "+f"(d[1]), "+f"(d[2]), "+f"(d[3])
                 : "r"(a[0]), "r"(a[1]), "r"(a[2]), "r"(a[3]), "r"(b[0]), "r"(b[1]));
}

// ===================== device scratch (no allocations) ======================
__device__ __align__(16) float g_proj[VV * H3];
__device__ __align__(16) float g_h1 [BB * HH];
__device__ __align__(16) float g_h2 [BB * HH];
__device__ __align__(16) float g_in1[BB * H3];
__device__ __align__(16) float g_xg2[BB * H3];
__device__ __align__(16) float g_in2[BB * H3];
__device__ int g_bar_cnt[1];   // zeroed by cudaMemsetAsync before the loop launch

__device__ __align__(16) __nv_bfloat16 g_h1h[BB * HH], g_h1l[BB * HH];
__device__ __align__(16) __nv_bfloat16 g_h2h[BB * HH], g_h2l[BB * HH];
__device__ __align__(16) __nv_bfloat16 g_seqh[(size_t)BB * TT * HH], g_seql[(size_t)BB * TT * HH];
__device__ __align__(16) __nv_bfloat16 g_ench[BB * ENCC], g_encl[BB * ENCC];

__device__ __align__(16) __nv_bfloat16 g_k1h [H3 * EE],   g_k1l [H3 * EE];
__device__ __align__(16) __nv_bfloat16 g_rk1h[H3 * HH],   g_rk1l[H3 * HH];
__device__ __align__(16) __nv_bfloat16 g_k2h [H3 * HH],   g_k2l [H3 * HH];
__device__ __align__(16) __nv_bfloat16 g_rk2h[H3 * HH],   g_rk2l[H3 * HH];
__device__ __align__(16) __nv_bfloat16 g_wi1h[HH * ENCC], g_wi1l[HH * ENCC];
__device__ __align__(16) __nv_bfloat16 g_wi2h[HH * ENCC], g_wi2l[HH * ENCC];
__device__ __align__(16) __nv_bfloat16 g_wvh [VV * HH],   g_wvl [VV * HH];
__device__ __align__(16) __nv_bfloat16 g_embh[VV * EE],   g_embl[VV * EE];

__device__ __forceinline__ void split2(float v, __nv_bfloat16& h, __nv_bfloat16& l) {
    h = __float2bfloat16(v);
    l = __float2bfloat16(v - __bfloat162float(h));
}

// ===================== prep: transpose + hi/lo split ========================
__global__ __launch_bounds__(256)
void tsplit_kernel(const float* __restrict__ W, __nv_bfloat16* __restrict__ Th,
                   __nv_bfloat16* __restrict__ Tl, int K, int N) {
    __shared__ float s[32][33];
    int n0 = blockIdx.x * 32, k0 = blockIdx.y * 32;
    int tx = threadIdx.x & 31, ty = threadIdx.x >> 5;
#pragma unroll
    for (int i = 0; i < 32; i += 8)
        s[ty + i][tx] = W[(size_t)(k0 + ty + i) * N + n0 + tx];
    __syncthreads();
#pragma unroll
    for (int i = 0; i < 32; i += 8) {
        float v = s[tx][ty + i];
        __nv_bfloat16 h, l; split2(v, h, l);
        size_t o = (size_t)(n0 + ty + i) * K + k0 + tx;
        Th[o] = h; Tl[o] = l;
    }
}

__global__ __launch_bounds__(256)
void tsplit3_kernel(const float* __restrict__ W0, __nv_bfloat16* __restrict__ Th0, __nv_bfloat16* __restrict__ Tl0,
                    const float* __restrict__ W1, __nv_bfloat16* __restrict__ Th1, __nv_bfloat16* __restrict__ Tl1,
                    const float* __restrict__ W2, __nv_bfloat16* __restrict__ Th2, __nv_bfloat16* __restrict__ Tl2) {
    const float* W = (blockIdx.z == 0) ? W0 : (blockIdx.z == 1) ? W1 : W2;
    __nv_bfloat16* Th = (blockIdx.z == 0) ? Th0 : (blockIdx.z == 1) ? Th1 : Th2;
    __nv_bfloat16* Tl = (blockIdx.z == 0) ? Tl0 : (blockIdx.z == 1) ? Tl1 : Tl2;
    const int K = HH, N = H3;
    __shared__ float s[32][33];
    int n0 = blockIdx.x * 32, k0 = blockIdx.y * 32;
    int tx = threadIdx.x & 31, ty = threadIdx.x >> 5;
#pragma unroll
    for (int i = 0; i < 32; i += 8)
        s[ty + i][tx] = W[(size_t)(k0 + ty + i) * N + n0 + tx];
    __syncthreads();
#pragma unroll
    for (int i = 0; i < 32; i += 8) {
        float v = s[tx][ty + i];
        __nv_bfloat16 h, l; split2(v, h, l);
        size_t o = (size_t)(n0 + ty + i) * K + k0 + tx;
        Th[o] = h; Tl[o] = l;
    }
}

__global__ __launch_bounds__(256)
void split_kernel(const float* __restrict__ src, __nv_bfloat16* __restrict__ dh,
                  __nv_bfloat16* __restrict__ dl, int n4) {
    int i = blockIdx.x * 256 + threadIdx.x;
    if (i >= n4) return;
    float4 v = ((const float4*)src)[i];
    __nv_bfloat16 h0,l0,h1,l1,h2,l2,h3,l3;
    split2(v.x,h0,l0); split2(v.y,h1,l1); split2(v.z,h2,l2); split2(v.w,h3,l3);
    ((__nv_bfloat162*)dh)[2*i]   = __nv_bfloat162(h0,h1);
    ((__nv_bfloat162*)dh)[2*i+1] = __nv_bfloat162(h2,h3);
    ((__nv_bfloat162*)dl)[2*i]   = __nv_bfloat162(l0,l1);
    ((__nv_bfloat162*)dl)[2*i+1] = __nv_bfloat162(l2,l3);
}

// ===================== shared GEMM tile machinery ===========================
#define LDP       40
#define TILE_B    (128 * LDP * 2)
#define STAGE_B   (4 * TILE_B)
#define SMEM_DYN  (2 * STAGE_B)          // 81920 bytes

struct TJob {
    const __nv_bfloat16 *Ah, *Al;   // [M,K]
    const __nv_bfloat16 *Bh, *Bl;   // [N,K]
    const float* bias;
    float* C;
    __nv_bfloat16 *Ch, *Cl;
};

// standalone GEMM kernel (prologue / logits / fallback step loop)
__global__ __launch_bounds__(256, 2)
void tc_gemm(TJob j0, TJob j1, TJob j2, int K, int N) {
    extern __shared__ __align__(16) char smem[];
    const TJob& jb = (blockIdx.z == 0) ? j0 : (blockIdx.z == 1) ? j1 : j2;
    const uint32_t sb = smem_u32(smem);
    const int tid = threadIdx.x;
    const int lane = tid & 31, warp = tid >> 5;
    const int wm = warp & 1, wn = warp >> 1;
    const int bm = blockIdx.y * 128, bn = blockIdx.x * 128;
    const int kch = K / 32;

    auto issue = [&](int c) {
        const int k0 = c * 32;
        const uint32_t st = sb + (c & 1) * STAGE_B;
#pragma unroll
        for (int i = 0; i < 8; i++) {
            const int tile = i >> 1;
            const int w = (i & 1) ? (tid + 256) & 511 : tid;
            const int row = w >> 2, c16 = w & 3;
            const __nv_bfloat16* src = (tile == 0) ? jb.Ah : (tile == 1) ? jb.Al
                                     : (tile == 2) ? jb.Bh : jb.Bl;
            const int roff = (tile < 2) ? bm : bn;
            cp_async16(st + tile * TILE_B + (row * LDP + c16 * 8) * 2,
                       src + (size_t)(roff + row) * K + k0 + c16 * 8);
        }
    };

    float acc[4][4][4];
#pragma unroll
    for (int i = 0; i < 4; i++)
#pragma unroll
        for (int j = 0; j < 4; j++)
#pragma unroll
            for (int q = 0; q < 4; q++) acc[i][j][q] = 0.f;

    const int arow = lane & 15, acsel = (lane >> 4) * 8;
    const int brow4 = lane & 7;
    const int bksel = ((lane >> 3) & 1) * 8;
    const int bnsel = ((lane >> 4) & 1) * 8;

    issue(0); CP_COMMIT();

    for (int c = 0; c < kch; c++) {
        if (c + 1 < kch) issue(c + 1);
        CP_COMMIT();
        CP_WAIT1();
        __syncthreads();

        const uint32_t st = sb + (c & 1) * STAGE_B;
        const uint32_t ah = st,              al = st + TILE_B;
        const uint32_t bh = st + 2 * TILE_B, bl = st + 3 * TILE_B;
#pragma unroll
        for (int kt = 0; kt < 2; kt++) {
            uint32_t afh[4][4], bfh[2][4], bfl[2][4];
#pragma unroll
            for (int mt = 0; mt < 4; mt++)
                ldsm_x4(afh[mt], ah + ((wm * 64 + mt * 16 + arow) * LDP + kt * 16 + acsel) * 2);
#pragma unroll
            for (int p = 0; p < 2; p++) {
                ldsm_x4(bfh[p], bh + ((wn * 32 + p * 16 + bnsel + brow4) * LDP + kt * 16 + bksel) * 2);
                ldsm_x4(bfl[p], bl + ((wn * 32 + p * 16 + bnsel + brow4) * LDP + kt * 16 + bksel) * 2);
            }
#pragma unroll
            for (int mt = 0; mt < 4; mt++)
#pragma unroll
                for (int nt = 0; nt < 4; nt++) {
                    mma16816(acc[mt][nt], afh[mt], &bfh[nt >> 1][(nt & 1) * 2]);
                    mma16816(acc[mt][nt], afh[mt], &bfl[nt >> 1][(nt & 1) * 2]);
                }
            uint32_t afl[4][4];
#pragma unroll
            for (int mt = 0; mt < 4; mt++)
                ldsm_x4(afl[mt], al + ((wm * 64 + mt * 16 + arow) * LDP + kt * 16 + acsel) * 2);
#pragma unroll
            for (int mt = 0; mt < 4; mt++)
#pragma unroll
                for (int nt = 0; nt < 4; nt++)
                    mma16816(acc[mt][nt], afl[mt], &bfh[nt >> 1][(nt & 1) * 2]);
        }
        __syncthreads();
    }

    const int quad = lane >> 2, pair = lane & 3;
#pragma unroll
    for (int mt = 0; mt < 4; mt++) {
#pragma unroll
        for (int h = 0; h < 2; h++) {
            int row = bm + wm * 64 + mt * 16 + quad + h * 8;
            float* crow = jb.C + (size_t)row * N;
#pragma unroll
            for (int nt = 0; nt < 4; nt++) {
                int col = bn + wn * 32 + nt * 8 + pair * 2;
                float v0 = acc[mt][nt][2 * h]     + (jb.bias ? jb.bias[col]     : 0.f);
                float v1 = acc[mt][nt][2 * h + 1] + (jb.bias ? jb.bias[col + 1] : 0.f);
                *(float2*)(crow + col) = make_float2(v0, v1);
                if (jb.Ch) {
                    __nv_bfloat16 h0, l0, h1, l1;
                    split2(v0, h0, l0); split2(v1, h1, l1);
                    *(__nv_bfloat162*)(jb.Ch + (size_t)row * N + col) = __nv_bfloat162(h0, h1);
                    *(__nv_bfloat162*)(jb.Cl + (size_t)row * N + col) = __nv_bfloat162(l0, l1);
                }
            }
        }
    }
}

// device-side tile GEMM for the persistent loop (K=HH fixed, N=H3 stride)
__device__ __forceinline__ void gemm_tile_512(
    const __nv_bfloat16* Ah, const __nv_bfloat16* Al,
    const __nv_bfloat16* Bh, const __nv_bfloat16* Bl,
    const float* bias, float* C, int bm, int bn, uint32_t sb)
{
    const int tid = threadIdx.x;
    const int lane = tid & 31, warp = tid >> 5;
    const int wm = warp & 1, wn = warp >> 1;
    const int kch = HH / 32;   // 16

    auto issue = [&](int c) {
        const int k0 = c * 32;
        const uint32_t st = sb + (c & 1) * STAGE_B;
#pragma unroll
        for (int i = 0; i < 8; i++) {
            const int tile = i >> 1;
            const int w = (i & 1) ? (tid + 256) & 511 : tid;
            const int row = w >> 2, c16 = w & 3;
            const __nv_bfloat16* src = (tile == 0) ? Ah : (tile == 1) ? Al
                                     : (tile == 2) ? Bh : Bl;
            const int roff = (tile < 2) ? bm : bn;
            cp_async16(st + tile * TILE_B + (row * LDP + c16 * 8) * 2,
                       src + (size_t)(roff + row) * HH + k0 + c16 * 8);
        }
    };

    float acc[4][4][4];
#pragma unroll
    for (int i = 0; i < 4; i++)
#pragma unroll
        for (int j = 0; j < 4; j++)
#pragma unroll
            for (int q = 0; q < 4; q++) acc[i][j][q] = 0.f;

    const int arow = lane & 15, acsel = (lane >> 4) * 8;
    const int brow4 = lane & 7;
    const int bksel = ((lane >> 3) & 1) * 8;
    const int bnsel = ((lane >> 4) & 1) * 8;

    issue(0); CP_COMMIT();

    for (int c = 0; c < kch; c++) {
        if (c + 1 < kch) issue(c + 1);
        CP_COMMIT();
        CP_WAIT1();
        __syncthreads();

        const uint32_t st = sb + (c & 1) * STAGE_B;
        const uint32_t ah = st,              al = st + TILE_B;
        const uint32_t bh = st + 2 * TILE_B, bl = st + 3 * TILE_B;
#pragma unroll
        for (int kt = 0; kt < 2; kt++) {
            uint32_t afh[4][4], bfh[2][4], bfl[2][4];
#pragma unroll
            for (int mt = 0; mt < 4; mt++)
                ldsm_x4(afh[mt], ah + ((wm * 64 + mt * 16 + arow) * LDP + kt * 16 + acsel) * 2);
#pragma unroll
            for (int p = 0; p < 2; p++) {
                ldsm_x4(bfh[p], bh + ((wn * 32 + p * 16 + bnsel + brow4) * LDP + kt * 16 + bksel) * 2);
                ldsm_x4(bfl[p], bl + ((wn * 32 + p * 16 + bnsel + brow4) * LDP + kt * 16 + bksel) * 2);
            }
#pragma unroll
            for (int mt = 0; mt < 4; mt++)
#pragma unroll
                for (int nt = 0; nt < 4; nt++) {
                    mma16816(acc[mt][nt], afh[mt], &bfh[nt >> 1][(nt & 1) * 2]);
                    mma16816(acc[mt][nt], afh[mt], &bfl[nt >> 1][(nt & 1) * 2]);
                }
            uint32_t afl[4][4];
#pragma unroll
            for (int mt = 0; mt < 4; mt++)
                ldsm_x4(afl[mt], al + ((wm * 64 + mt * 16 + arow) * LDP + kt * 16 + acsel) * 2);
#pragma unroll
            for (int mt = 0; mt < 4; mt++)
#pragma unroll
                for (int nt = 0; nt < 4; nt++)
                    mma16816(acc[mt][nt], afl[mt], &bfh[nt >> 1][(nt & 1) * 2]);
        }
        __syncthreads();
    }

    const int quad = lane >> 2, pair = lane & 3;
#pragma unroll
    for (int mt = 0; mt < 4; mt++) {
#pragma unroll
        for (int h = 0; h < 2; h++) {
            int row = bm + wm * 64 + mt * 16 + quad + h * 8;
            float* crow = C + (size_t)row * H3;
#pragma unroll
            for (int nt = 0; nt < 4; nt++) {
                int col = bn + wn * 32 + nt * 8 + pair * 2;
                *(float2*)(crow + col) = make_float2(acc[mt][nt][2*h]   + bias[col],
                                                     acc[mt][nt][2*h+1] + bias[col + 1]);
            }
        }
    }
}

// ===================== gate update helpers ==================================
__device__ __forceinline__ float sigm_(float x) { return 1.f / (1.f + expf(-x)); }

__device__ __forceinline__ void gate4(const float4& xz, const float4& xr, const float4& xh,
                                      const float4& rz, const float4& rr, const float4& rh,
                                      float4& hv) {
    float z, r, hg;
    z = sigm_(xz.x + rz.x); r = sigm_(xr.x + rr.x); hg = tanhf(xh.x + r * rh.x); hv.x = z * hv.x + (1.f - z) * hg;
    z = sigm_(xz.y + rz.y); r = sigm_(xr.y + rr.y); hg = tanhf(xh.y + r * rh.y); hv.y = z * hv.y + (1.f - z) * hg;
    z = sigm_(xz.z + rz.z); r = sigm_(xr.z + rr.z); hg = tanhf(xh.z + r * rh.z); hv.z = z * hv.z + (1.f - z) * hg;
    z = sigm_(xz.w + rz.w); r = sigm_(xr.w + rr.w); hg = tanhf(xh.w + r * rh.w); hv.w = z * hv.w + (1.f - z) * hg;
}
__device__ __forceinline__ void store_split4(const float4& hv, __nv_bfloat16* ph, __nv_bfloat16* pl) {
    __nv_bfloat16 a0,b0,a1,b1,a2,b2,a3,b3;
    split2(hv.x,a0,b0); split2(hv.y,a1,b1); split2(hv.z,a2,b2); split2(hv.w,a3,b3);
    *(__nv_bfloat162*)(ph)     = __nv_bfloat162(a0,a1);
    *(__nv_bfloat162*)(ph + 2) = __nv_bfloat162(a2,a3);
    *(__nv_bfloat162*)(pl)     = __nv_bfloat162(b0,b1);
    *(__nv_bfloat162*)(pl + 2) = __nv_bfloat162(b2,b3);
}

// layer-1-only update (t=0 bootstrap)
__global__ __launch_bounds__(256)
void gru_step1(const float* __restrict__ proj, const int* __restrict__ tgt, int t1,
               const float* __restrict__ in1, float* __restrict__ h1,
               __nv_bfloat16* __restrict__ h1h, __nv_bfloat16* __restrict__ h1l) {
    int idx = blockIdx.x * 256 + threadIdx.x;
    int b = idx >> 7;
    int j = (idx & 127) * 4;
    size_t hidx = (size_t)b * HH + j;
    int tok = tgt[b * TT + t1];
    if (tok != 0) {
        float4 hv = *(float4*)(h1 + hidx);
        const float* xg = proj + (size_t)tok * H3;
        const float* in = in1 + (size_t)b * H3;
        gate4(*(const float4*)(xg + j), *(const float4*)(xg + HH + j), *(const float4*)(xg + 2*HH + j),
              *(const float4*)(in + j), *(const float4*)(in + HH + j), *(const float4*)(in + 2*HH + j), hv);
        *(float4*)(h1 + hidx) = hv;
        store_split4(hv, h1h + hidx, h1l + hidx);
    }
}

// fused two-layer update (fallback per-step path, identical to R8's gru_step)
__global__ __launch_bounds__(256)
void gru_step_full(const float* __restrict__ proj, const int* __restrict__ tgt,
                   int t1, const float* __restrict__ in1, float* __restrict__ h1,
                   __nv_bfloat16* __restrict__ h1h, __nv_bfloat16* __restrict__ h1l,
                   int t2, const float* __restrict__ xg2, const float* __restrict__ in2,
                   float* __restrict__ h2,
                   __nv_bfloat16* __restrict__ h2h, __nv_bfloat16* __restrict__ h2l,
                   __nv_bfloat16* __restrict__ seqh, __nv_bfloat16* __restrict__ seql) {
    int idx = blockIdx.x * 256 + threadIdx.x;
    int b = idx >> 7;
    int j = (idx & 127) * 4;
    size_t hidx = (size_t)b * HH + j;

    {
        float4 hv = *(float4*)(h2 + hidx);
        if (tgt[b * TT + t2] != 0) {
            const float* xg = xg2 + (size_t)b * H3;
            const float* in = in2 + (size_t)b * H3;
            gate4(*(const float4*)(xg + j), *(const float4*)(xg + HH + j), *(const float4*)(xg + 2*HH + j),
                  *(const float4*)(in + j), *(const float4*)(in + HH + j), *(const float4*)(in + 2*HH + j), hv);
            *(float4*)(h2 + hidx) = hv;
            store_split4(hv, h2h + hidx, h2l + hidx);
        }
        size_t so = (size_t)b * (TT * HH) + (size_t)t2 * HH + j;
        store_split4(hv, seqh + so, seql + so);
    }
    if (t1 < TT) {
        int tok = tgt[b * TT + t1];
        if (tok != 0) {
            float4 hv = *(float4*)(h1 + hidx);
            const float* xg = proj + (size_t)tok * H3;
            const float* in = in1 + (size_t)b * H3;
            gate4(*(const float4*)(xg + j), *(const float4*)(xg + HH + j), *(const float4*)(xg + 2*HH + j),
                  *(const float4*)(in + j), *(const float4*)(in + HH + j), *(const float4*)(in + 2*HH + j), hv);
            *(float4*)(h1 + hidx) = hv;
            store_split4(hv, h1h + hidx, h1l + hidx);
        }
    }
}

// ===================== persistent 48-step loop kernel =======================
__device__ __forceinline__ void grid_bar(unsigned gen) {
    __threadfence();
    __syncthreads();
    if (threadIdx.x == 0) {
        atomicAdd(&g_bar_cnt[0], 1);
        while ((unsigned)(*(volatile int*)&g_bar_cnt[0]) < gen * NCTA) __nanosleep(100);
        __threadfence();
    }
    __syncthreads();
}

__global__ __launch_bounds__(256, 2)
void loop_kernel(const __nv_bfloat16* __restrict__ k2h,  const __nv_bfloat16* __restrict__ k2l,
                 const __nv_bfloat16* __restrict__ rk2h, const __nv_bfloat16* __restrict__ rk2l,
                 const __nv_bfloat16* __restrict__ rk1h, const __nv_bfloat16* __restrict__ rk1l,
                 const float* __restrict__ b1, const float* __restrict__ b2,
                 __nv_bfloat16* h1h, __nv_bfloat16* h1l,
                 __nv_bfloat16* h2h, __nv_bfloat16* h2l,
                 float* xg2, float* in2, float* in1,
                 float* h1, float* h2,
                 const float* __restrict__ proj, const int* __restrict__ tgt,
                 __nv_bfloat16* seqh, __nv_bfloat16* seql) {
    extern __shared__ __align__(16) char smem[];
    const uint32_t sb = smem_u32(smem);
    const int tid = threadIdx.x;
    unsigned gen = 0;

    for (int t = 0; t < TT; t++) {
        const int ntiles = (t == TT - 1) ? 384 : 576;
        for (int tile = blockIdx.x; tile < ntiles; tile += NCTA) {
            const int job = tile / 192, rem = tile - job * 192;
            const int bm = (rem / 12) * 128, bn = (rem % 12) * 128;
            if (job == 0)
                gemm_tile_512(h1h, h1l, k2h,  k2l,  b2,      xg2, bm, bn, sb);
            else if (job == 1)
                gemm_tile_512(h2h, h2l, rk2h, rk2l, b2 + H3, in2, bm, bn, sb);
            else
                gemm_tile_512(h1h, h1l, rk1h, rk1l, b1 + H3, in1, bm, bn, sb);
        }
        grid_bar(++gen);

        for (int u = blockIdx.x * 256 + tid; u < BB * HH / 4; u += NCTA * 256) {
            const int b = u >> 7;
            const int j = (u & 127) * 4;
            const size_t hidx = (size_t)b * HH + j;

            float4 hv = *(float4*)(h2 + hidx);
            if (tgt[b * TT + t] != 0) {
                const float* xg = xg2 + (size_t)b * H3;
                const float* in = in2 + (size_t)b * H3;
                gate4(__ldcg((const float4*)(xg + j)), __ldcg((const float4*)(xg + HH + j)),
                      __ldcg((const float4*)(xg + 2*HH + j)),
                      __ldcg((const float4*)(in + j)), __ldcg((const float4*)(in + HH + j)),
                      __ldcg((const float4*)(in + 2*HH + j)), hv);
                *(float4*)(h2 + hidx) = hv;
                store_split4(hv, h2h + hidx, h2l + hidx);
            }
            size_t so = (size_t)b * (TT * HH) + (size_t)t * HH + j;
            store_split4(hv, seqh + so, seql + so);

            if (t + 1 < TT) {
                int tok = tgt[b * TT + t + 1];
                if (tok != 0) {
                    float4 h1v = *(float4*)(h1 + hidx);
                    const float* xg = proj + (size_t)tok * H3;
                    const float* in = in1 + (size_t)b * H3;
                    gate4(*(const float4*)(xg + j), *(const float4*)(xg + HH + j),
                          *(const float4*)(xg + 2*HH + j),
                          __ldcg((const float4*)(in + j)), __ldcg((const float4*)(in + HH + j)),
                          __ldcg((const float4*)(in + 2*HH + j)), h1v);
                    *(float4*)(h1 + hidx) = h1v;
                    store_split4(h1v, h1h + hidx, h1l + hidx);
                }
            }
        }
        grid_bar(++gen);
    }
}

// ===================== softmax over V=128 ===================================
__global__ __launch_bounds__(256)
void softmax_kernel(float* __restrict__ out) {
    int row  = blockIdx.x * 8 + (threadIdx.x >> 5);
    int lane = threadIdx.x & 31;
    float* p = out + (size_t)row * VV + lane * 4;
    float4 v = *(float4*)p;
    float m = fmaxf(fmaxf(v.x, v.y), fmaxf(v.z, v.w));
#pragma unroll
    for (int o = 16; o > 0; o >>= 1) m = fmaxf(m, __shfl_xor_sync(0xffffffffu, m, o));
    v.x = expf(v.x - m); v.y = expf(v.y - m); v.z = expf(v.z - m); v.w = expf(v.w - m);
    float s = v.x + v.y + v.z + v.w;
#pragma unroll
    for (int o = 16; o > 0; o >>= 1) s += __shfl_xor_sync(0xffffffffu, s, o);
    float inv = 1.f / s;
    v.x *= inv; v.y *= inv; v.z *= inv; v.w *= inv;
    *(float4*)p = v;
}

// ===================== launch ===============================================
static void* sym(const void* s) { void* p; cudaGetSymbolAddress(&p, s); return p; }

extern "C" void kernel_launch(void* const* d_in, const int* in_sizes, int n_in,
                              void* d_out, int out_size) {
    const int*   tgt = (const int*)  d_in[0];
    const float* enc = (const float*)d_in[1];
    const float* Wi1 = (const float*)d_in[2];
    const float* Wi2 = (const float*)d_in[3];
    const float* emb = (const float*)d_in[4];
    const float* k1  = (const float*)d_in[5];
    const float* rk1 = (const float*)d_in[6];
    const float* b1  = (const float*)d_in[7];
    const float* k2  = (const float*)d_in[8];
    const float* rk2 = (const float*)d_in[9];
    const float* b2  = (const float*)d_in[10];
    const float* Wv  = (const float*)d_in[11];
    const float* bv  = (const float*)d_in[12];
    float* out = (float*)d_out;

    float* proj = (float*)sym(g_proj);
    float* h1  = (float*)sym(g_h1);   float* h2  = (float*)sym(g_h2);
    float* in1 = (float*)sym(g_in1);  float* xg2 = (float*)sym(g_xg2);  float* in2 = (float*)sym(g_in2);
    int*   barp = (int*)sym(g_bar_cnt);
    __nv_bfloat16 *h1h=(__nv_bfloat16*)sym(g_h1h), *h1l=(__nv_bfloat16*)sym(g_h1l);
    __nv_bfloat16 *h2h=(__nv_bfloat16*)sym(g_h2h), *h2l=(__nv_bfloat16*)sym(g_h2l);
    __nv_bfloat16 *sqh=(__nv_bfloat16*)sym(g_seqh), *sql=(__nv_bfloat16*)sym(g_seql);
    __nv_bfloat16 *ench=(__nv_bfloat16*)sym(g_ench), *encl=(__nv_bfloat16*)sym(g_encl);
    __nv_bfloat16 *k1h=(__nv_bfloat16*)sym(g_k1h),   *k1l=(__nv_bfloat16*)sym(g_k1l);
    __nv_bfloat16 *rk1h=(__nv_bfloat16*)sym(g_rk1h), *rk1l=(__nv_bfloat16*)sym(g_rk1l);
    __nv_bfloat16 *k2h=(__nv_bfloat16*)sym(g_k2h),   *k2l=(__nv_bfloat16*)sym(g_k2l);
    __nv_bfloat16 *rk2h=(__nv_bfloat16*)sym(g_rk2h), *rk2l=(__nv_bfloat16*)sym(g_rk2l);
    __nv_bfloat16 *wi1h=(__nv_bfloat16*)sym(g_wi1h), *wi1l=(__nv_bfloat16*)sym(g_wi1l);
    __nv_bfloat16 *wi2h=(__nv_bfloat16*)sym(g_wi2h), *wi2l=(__nv_bfloat16*)sym(g_wi2l);
    __nv_bfloat16 *wvh=(__nv_bfloat16*)sym(g_wvh),   *wvl=(__nv_bfloat16*)sym(g_wvl);
    __nv_bfloat16 *embh=(__nv_bfloat16*)sym(g_embh), *embl=(__nv_bfloat16*)sym(g_embl);

    cudaFuncSetAttribute(tc_gemm,     cudaFuncAttributeMaxDynamicSharedMemorySize, SMEM_DYN);
    cudaFuncSetAttribute(loop_kernel, cudaFuncAttributeMaxDynamicSharedMemorySize, SMEM_DYN);

    // residency guard: persistent path only if all NCTA blocks can be co-resident
    int occ = 0, nsm = 0;
    cudaOccupancyMaxActiveBlocksPerMultiprocessor(&occ, loop_kernel, 256, SMEM_DYN);
    cudaDeviceGetAttribute(&nsm, cudaDevAttrMultiProcessorCount, 0);
    const bool persistent = (occ * nsm >= NCTA);

    dim3 blk(256);

    // ---- prep ----
    tsplit_kernel<<<dim3(HH/32, ENCC/32),blk>>>(Wi1, wi1h, wi1l, ENCC, HH);
    tsplit_kernel<<<dim3(HH/32, ENCC/32),blk>>>(Wi2, wi2h, wi2l, ENCC, HH);
    split_kernel<<<(BB*ENCC/4 + 255)/256, blk>>>(enc, ench, encl, BB*ENCC/4);
    tsplit_kernel<<<dim3(H3/32, EE/32),  blk>>>(k1,  k1h,  k1l,  EE,   H3);
    split_kernel<<<(VV*EE/4 + 255)/256,   blk>>>(emb, embh, embl, VV*EE/4);

    // h0 init
    {
        TJob a = {ench, encl, wi1h, wi1l, nullptr, h1, h1h, h1l};
        TJob b = {ench, encl, wi2h, wi2l, nullptr, h2, h2h, h2l};
        tc_gemm<<<dim3(HH/128, BB/128, 2), blk, SMEM_DYN>>>(a, b, a, ENCC, HH);
    }

    tsplit3_kernel<<<dim3(H3/32, HH/32, 3), blk>>>(rk1, rk1h, rk1l,
                                                   k2,  k2h,  k2l,
                                                   rk2, rk2h, rk2l);
    tsplit_kernel<<<dim3(VV/32, HH/32),  blk>>>(Wv,  wvh,  wvl,  HH,   VV);

    // proj = emb_table @ k1 + b1[0]
    {
        TJob a = {embh, embl, k1h, k1l, b1, proj, nullptr, nullptr};
        tc_gemm<<<dim3(H3/128, 1, 1), blk, SMEM_DYN>>>(a, a, a, EE, H3);
    }
    // inner1(t=0) = h1 @ rk1 + b1[1]
    {
        TJob a = {h1h, h1l, rk1h, rk1l, b1 + H3, in1, nullptr, nullptr};
        tc_gemm<<<dim3(H3/128, BB/128, 1), blk, SMEM_DYN>>>(a, a, a, HH, H3);
    }
    const int gblocks = BB * HH / 4 / 256;  // 1024
    gru_step1<<<gblocks, blk>>>(proj, tgt, 0, in1, h1, h1h, h1l);

    if (persistent) {
        cudaMemsetAsync(barp, 0, sizeof(int));
        loop_kernel<<<NCTA, blk, SMEM_DYN>>>(k2h, k2l, rk2h, rk2l, rk1h, rk1l,
                                             b1, b2, h1h, h1l, h2h, h2l,
                                             xg2, in2, in1, h1, h2,
                                             proj, tgt, sqh, sql);
    } else {
        for (int t = 0; t < TT; t++) {
            TJob a = {h1h, h1l, k2h,  k2l,  b2,      xg2, nullptr, nullptr};
            TJob b = {h2h, h2l, rk2h, rk2l, b2 + H3, in2, nullptr, nullptr};
            TJob c = {h1h, h1l, rk1h, rk1l, b1 + H3, in1, nullptr, nullptr};
            int nz = (t == TT - 1) ? 2 : 3;
            tc_gemm<<<dim3(H3/128, BB/128, nz), blk, SMEM_DYN>>>(a, b, c, HH, H3);
            gru_step_full<<<gblocks, blk>>>(proj, tgt, t + 1, in1, h1, h1h, h1l,
                                            t, xg2, in2, h2, h2h, h2l, sqh, sql);
        }
    }

    // ---- logits + softmax ----
    {
        TJob a = {sqh, sql, wvh, wvl, bv, out, nullptr, nullptr};
        tc_gemm<<<dim3(VV/128, (BB*TT)/128, 1), blk, SMEM_DYN>>>(a, a, a, HH, VV);
    }
    softmax_kernel<<<(BB*TT)/8, blk>>>(out);
}

// round 12
// speedup vs baseline: 1.1372x; 1.1372x over previous
#include <cuda_runtime.h>
#include <cuda_bf16.h>
#include <stdint.h>
#include <math.h>

#define BB   2048
#define TT   48
#define HH   512
#define EE   256
#define VV   128
#define ENCC 1024
#define H3   1536

// ===================== stable-ISA PTX helpers (sm_80+) ======================
__device__ __forceinline__ uint32_t smem_u32(const void* p) {
    uint32_t a;
    asm("{ .reg .u64 t; cvta.to.shared.u64 t, %1; cvt.u32.u64 %0, t; }" : "=r"(a) : "l"(p));
    return a;
}
__device__ __forceinline__ void cp_async16(uint32_t dst, const void* src) {
    asm volatile("cp.async.cg.shared.global [%0], [%1], 16;" :: "r"(dst), "l"(src));
}
#define CP_COMMIT() asm volatile("cp.async.commit_group;" ::: "memory")
#define CP_WAIT1()  asm volatile("cp.async.wait_group 1;" ::: "memory")

__device__ __forceinline__ void ldsm_x4(uint32_t* r, uint32_t addr) {
    asm volatile("ldmatrix.sync.aligned.m8n8.x4.shared.b16 {%0,%1,%2,%3}, [%4];"
                 : "=r"(r[0]), "=r"(r[1]), "=r"(r[2]), "=r"(r[3]) : "r"(addr));
}
__device__ __forceinline__ void mma16816(float* d, const uint32_t* a, const uint32_t* b) {
    asm volatile("mma.sync.aligned.m16n8k16.row.col.f32.bf16.bf16.f32 "
                 "{%0,%1,%2,%3}, {%4,%5,%6,%7}, {%8,%9}, {%0,%1,%2,%3};"
                 : "+f"(d[0]), "+f"(d[1]), "+f"(d[2]), "+f"(d[3])
                 : "r"(a[0]), "r"(a[1]), "r"(a[2]), "r"(a[3]), "r"(b[0]), "r"(b[1]));
}

// ===================== device scratch (no allocations) ======================
__device__ __align__(16) float g_proj[VV * H3];
__device__ __align__(16) float g_h1 [BB * HH];
__device__ __align__(16) float g_h2 [BB * HH];
__device__ __align__(16) float g_in1[BB * H3];
__device__ __align__(16) float g_xg2[BB * H3];
__device__ __align__(16) float g_in2[BB * H3];

__device__ __align__(16) __nv_bfloat16 g_h1h[BB * HH], g_h1l[BB * HH];
__device__ __align__(16) __nv_bfloat16 g_h2h[BB * HH], g_h2l[BB * HH];
__device__ __align__(16) __nv_bfloat16 g_seqh[(size_t)BB * TT * HH], g_seql[(size_t)BB * TT * HH];
__device__ __align__(16) __nv_bfloat16 g_ench[BB * ENCC], g_encl[BB * ENCC];

__device__ __align__(16) __nv_bfloat16 g_k1h [H3 * EE],   g_k1l [H3 * EE];
__device__ __align__(16) __nv_bfloat16 g_rk1h[H3 * HH],   g_rk1l[H3 * HH];
__device__ __align__(16) __nv_bfloat16 g_k2h [H3 * HH],   g_k2l [H3 * HH];
__device__ __align__(16) __nv_bfloat16 g_rk2h[H3 * HH],   g_rk2l[H3 * HH];
__device__ __align__(16) __nv_bfloat16 g_wi1h[HH * ENCC], g_wi1l[HH * ENCC];
__device__ __align__(16) __nv_bfloat16 g_wi2h[HH * ENCC], g_wi2l[HH * ENCC];
__device__ __align__(16) __nv_bfloat16 g_wvh [VV * HH],   g_wvl [VV * HH];
__device__ __align__(16) __nv_bfloat16 g_embh[VV * EE],   g_embl[VV * EE];

__device__ __forceinline__ void split2(float v, __nv_bfloat16& h, __nv_bfloat16& l) {
    h = __float2bfloat16(v);
    l = __float2bfloat16(v - __bfloat162float(h));
}

// ===================== prep: transpose + hi/lo split ========================
__global__ __launch_bounds__(256)
void tsplit_kernel(const float* __restrict__ W, __nv_bfloat16* __restrict__ Th,
                   __nv_bfloat16* __restrict__ Tl, int K, int N) {
    __shared__ float s[32][33];
    int n0 = blockIdx.x * 32, k0 = blockIdx.y * 32;
    int tx = threadIdx.x & 31, ty = threadIdx.x >> 5;
#pragma unroll
    for (int i = 0; i < 32; i += 8)
        s[ty + i][tx] = W[(size_t)(k0 + ty + i) * N + n0 + tx];
    __syncthreads();
#pragma unroll
    for (int i = 0; i < 32; i += 8) {
        float v = s[tx][ty + i];
        __nv_bfloat16 h, l; split2(v, h, l);
        size_t o = (size_t)(n0 + ty + i) * K + k0 + tx;
        Th[o] = h; Tl[o] = l;
    }
}

__global__ __launch_bounds__(256)
void tsplit3_kernel(const float* __restrict__ W0, __nv_bfloat16* __restrict__ Th0, __nv_bfloat16* __restrict__ Tl0,
                    const float* __restrict__ W1, __nv_bfloat16* __restrict__ Th1, __nv_bfloat16* __restrict__ Tl1,
                    const float* __restrict__ W2, __nv_bfloat16* __restrict__ Th2, __nv_bfloat16* __restrict__ Tl2) {
    const float* W = (blockIdx.z == 0) ? W0 : (blockIdx.z == 1) ? W1 : W2;
    __nv_bfloat16* Th = (blockIdx.z == 0) ? Th0 : (blockIdx.z == 1) ? Th1 : Th2;
    __nv_bfloat16* Tl = (blockIdx.z == 0) ? Tl0 : (blockIdx.z == 1) ? Tl1 : Tl2;
    const int K = HH, N = H3;
    __shared__ float s[32][33];
    int n0 = blockIdx.x * 32, k0 = blockIdx.y * 32;
    int tx = threadIdx.x & 31, ty = threadIdx.x >> 5;
#pragma unroll
    for (int i = 0; i < 32; i += 8)
        s[ty + i][tx] = W[(size_t)(k0 + ty + i) * N + n0 + tx];
    __syncthreads();
#pragma unroll
    for (int i = 0; i < 32; i += 8) {
        float v = s[tx][ty + i];
        __nv_bfloat16 h, l; split2(v, h, l);
        size_t o = (size_t)(n0 + ty + i) * K + k0 + tx;
        Th[o] = h; Tl[o] = l;
    }
}

__global__ __launch_bounds__(256)
void split_kernel(const float* __restrict__ src, __nv_bfloat16* __restrict__ dh,
                  __nv_bfloat16* __restrict__ dl, int n4) {
    int i = blockIdx.x * 256 + threadIdx.x;
    if (i >= n4) return;
    float4 v = ((const float4*)src)[i];
    __nv_bfloat16 h0,l0,h1,l1,h2,l2,h3,l3;
    split2(v.x,h0,l0); split2(v.y,h1,l1); split2(v.z,h2,l2); split2(v.w,h3,l3);
    ((__nv_bfloat162*)dh)[2*i]   = __nv_bfloat162(h0,h1);
    ((__nv_bfloat162*)dh)[2*i+1] = __nv_bfloat162(h2,h3);
    ((__nv_bfloat162*)dl)[2*i]   = __nv_bfloat162(l0,l1);
    ((__nv_bfloat162*)dl)[2*i+1] = __nv_bfloat162(l2,l3);
}

// ===================== mma.sync split-bf16 GEMM =============================
// 3-stage cp.async pipeline, XOR-swizzled SMEM (64B rows, no padding),
// single __syncthreads per K-chunk. Math identical to the R8 kernel.
#define TILE_B    (128 * 32 * 2)         // 8192 bytes per operand tile
#define STAGE_B   (4 * TILE_B)           // Ah, Al, Bh, Bl = 32768
#define SMEM_DYN  (3 * STAGE_B)          // 98304 bytes

// swizzled byte offset of 16B unit u in row r (row stride 64B, 4 units/row)
#define SWOFF(r, u) ((r) * 64 + (((u) ^ (((r) >> 1) & 3)) * 16))

struct TJob {
    const __nv_bfloat16 *Ah, *Al;   // [M,K]
    const __nv_bfloat16 *Bh, *Bl;   // [N,K]
    const float* bias;
    float* C;
    __nv_bfloat16 *Ch, *Cl;
};

__global__ __launch_bounds__(256, 2)
void tc_gemm(TJob j0, TJob j1, TJob j2, int K, int N) {
    extern __shared__ __align__(16) char smem[];
    const TJob& jb = (blockIdx.z == 0) ? j0 : (blockIdx.z == 1) ? j1 : j2;
    const uint32_t sb = smem_u32(smem);
    const int tid = threadIdx.x;
    const int lane = tid & 31, warp = tid >> 5;
    const int wm = warp & 1, wn = warp >> 1;           // warp tile 64x32
    const int bm = blockIdx.y * 128, bn = blockIdx.x * 128;
    const int kch = K / 32;                            // >= 8 for all our K

    // per-thread staging coords: 2048 16B-units per stage, 8 per thread
    auto issue = [&](int c) {
        const int k0 = c * 32;
        const uint32_t st = sb + (c % 3) * STAGE_B;
#pragma unroll
        for (int i = 0; i < 8; i++) {
            const int tile = i >> 1;
            const int w = (i & 1) ? (tid + 256) & 511 : tid;
            const int row = w >> 2, u = w & 3;
            const __nv_bfloat16* src = (tile == 0) ? jb.Ah : (tile == 1) ? jb.Al
                                     : (tile == 2) ? jb.Bh : jb.Bl;
            const int roff = (tile < 2) ? bm : bn;
            cp_async16(st + tile * TILE_B + SWOFF(row, u),
                       src + (size_t)(roff + row) * K + k0 + u * 8);
        }
    };

    float acc[4][4][4];
#pragma unroll
    for (int i = 0; i < 4; i++)
#pragma unroll
        for (int j = 0; j < 4; j++)
#pragma unroll
            for (int q = 0; q < 4; q++) acc[i][j][q] = 0.f;

    // ldmatrix lane coords
    const int arow = lane & 15, au = (lane >> 4);         // A x4: unit sel 0/1
    const int brow4 = lane & 7;
    const int bu = (lane >> 3) & 1;                        // B x4: unit sel 0/1
    const int bnsel = ((lane >> 4) & 1) * 8;               // row +0/+8

    issue(0); CP_COMMIT();
    issue(1); CP_COMMIT();

    for (int c = 0; c < kch; c++) {
        CP_WAIT1();               // groups <= c done (one pending allowed)
        __syncthreads();          // RAW for buf c%3 AND WAR before writing buf (c+2)%3
        if (c + 2 < kch) issue(c + 2);
        CP_COMMIT();

        const uint32_t st = sb + (c % 3) * STAGE_B;
        const uint32_t ah = st,              al = st + TILE_B;
        const uint32_t bh = st + 2 * TILE_B, bl = st + 3 * TILE_B;
#pragma unroll
        for (int kt = 0; kt < 2; kt++) {
            uint32_t afh[4][4], bfh[2][4], bfl[2][4];
#pragma unroll
            for (int mt = 0; mt < 4; mt++) {
                int r = wm * 64 + mt * 16 + arow;
                ldsm_x4(afh[mt], ah + SWOFF(r, kt * 2 + au));
            }
#pragma unroll
            for (int p = 0; p < 2; p++) {
                int r = wn * 32 + p * 16 + bnsel + brow4;
                ldsm_x4(bfh[p], bh + SWOFF(r, kt * 2 + bu));
                ldsm_x4(bfl[p], bl + SWOFF(r, kt * 2 + bu));
            }
#pragma unroll
            for (int mt = 0; mt < 4; mt++)
#pragma unroll
                for (int nt = 0; nt < 4; nt++) {
                    mma16816(acc[mt][nt], afh[mt], &bfh[nt >> 1][(nt & 1) * 2]);
                    mma16816(acc[mt][nt], afh[mt], &bfl[nt >> 1][(nt & 1) * 2]);
                }
            uint32_t afl[4][4];
#pragma unroll
            for (int mt = 0; mt < 4; mt++) {
                int r = wm * 64 + mt * 16 + arow;
                ldsm_x4(afl[mt], al + SWOFF(r, kt * 2 + au));
            }
#pragma unroll
            for (int mt = 0; mt < 4; mt++)
#pragma unroll
                for (int nt = 0; nt < 4; nt++)
                    mma16816(acc[mt][nt], afl[mt], &bfh[nt >> 1][(nt & 1) * 2]);
        }
        // no trailing sync: next iteration's WAIT1+sync covers the hazards
    }

    const int quad = lane >> 2, pair = lane & 3;
#pragma unroll
    for (int mt = 0; mt < 4; mt++) {
#pragma unroll
        for (int h = 0; h < 2; h++) {
            int row = bm + wm * 64 + mt * 16 + quad + h * 8;
            float* crow = jb.C + (size_t)row * N;
#pragma unroll
            for (int nt = 0; nt < 4; nt++) {
                int col = bn + wn * 32 + nt * 8 + pair * 2;
                float v0 = acc[mt][nt][2 * h]     + (jb.bias ? jb.bias[col]     : 0.f);
                float v1 = acc[mt][nt][2 * h + 1] + (jb.bias ? jb.bias[col + 1] : 0.f);
                *(float2*)(crow + col) = make_float2(v0, v1);
                if (jb.Ch) {
                    __nv_bfloat16 h0, l0, h1, l1;
                    split2(v0, h0, l0); split2(v1, h1, l1);
                    *(__nv_bfloat162*)(jb.Ch + (size_t)row * N + col) = __nv_bfloat162(h0, h1);
                    *(__nv_bfloat162*)(jb.Cl + (size_t)row * N + col) = __nv_bfloat162(l0, l1);
                }
            }
        }
    }
}

// ===================== fused GRU gate update ================================
__device__ __forceinline__ float sigm_(float x) { return 1.f / (1.f + expf(-x)); }

__device__ __forceinline__ void gate4(const float4& xz, const float4& xr, const float4& xh,
                                      const float4& rz, const float4& rr, const float4& rh,
                                      float4& hv) {
    float z, r, hg;
    z = sigm_(xz.x + rz.x); r = sigm_(xr.x + rr.x); hg = tanhf(xh.x + r * rh.x); hv.x = z * hv.x + (1.f - z) * hg;
    z = sigm_(xz.y + rz.y); r = sigm_(xr.y + rr.y); hg = tanhf(xh.y + r * rh.y); hv.y = z * hv.y + (1.f - z) * hg;
    z = sigm_(xz.z + rz.z); r = sigm_(xr.z + rr.z); hg = tanhf(xh.z + r * rh.z); hv.z = z * hv.z + (1.f - z) * hg;
    z = sigm_(xz.w + rz.w); r = sigm_(xr.w + rr.w); hg = tanhf(xh.w + r * rh.w); hv.w = z * hv.w + (1.f - z) * hg;
}
__device__ __forceinline__ void store_split4(const float4& hv, __nv_bfloat16* ph, __nv_bfloat16* pl) {
    __nv_bfloat16 a0,b0,a1,b1,a2,b2,a3,b3;
    split2(hv.x,a0,b0); split2(hv.y,a1,b1); split2(hv.z,a2,b2); split2(hv.w,a3,b3);
    *(__nv_bfloat162*)(ph)     = __nv_bfloat162(a0,a1);
    *(__nv_bfloat162*)(ph + 2) = __nv_bfloat162(a2,a3);
    *(__nv_bfloat162*)(pl)     = __nv_bfloat162(b0,b1);
    *(__nv_bfloat162*)(pl + 2) = __nv_bfloat162(b2,b3);
}

__global__ __launch_bounds__(256)
void gru_step1(const float* __restrict__ proj, const int* __restrict__ tgt, int t1,
               const float* __restrict__ in1, float* __restrict__ h1,
               __nv_bfloat16* __restrict__ h1h, __nv_bfloat16* __restrict__ h1l) {
    int idx = blockIdx.x * 256 + threadIdx.x;
    int b = idx >> 7;
    int j = (idx & 127) * 4;
    size_t hidx = (size_t)b * HH + j;
    int tok = tgt[b * TT + t1];
    if (tok != 0) {
        float4 hv = *(float4*)(h1 + hidx);
        const float* xg = proj + (size_t)tok * H3;
        const float* in = in1 + (size_t)b * H3;
        gate4(*(const float4*)(xg + j), *(const float4*)(xg + HH + j), *(const float4*)(xg + 2*HH + j),
              *(const float4*)(in + j), *(const float4*)(in + HH + j), *(const float4*)(in + 2*HH + j), hv);
        *(float4*)(h1 + hidx) = hv;
        store_split4(hv, h1h + hidx, h1l + hidx);
    }
}

__global__ __launch_bounds__(256)
void gru_step_full(const float* __restrict__ proj, const int* __restrict__ tgt,
                   int t1, const float* __restrict__ in1, float* __restrict__ h1,
                   __nv_bfloat16* __restrict__ h1h, __nv_bfloat16* __restrict__ h1l,
                   int t2, const float* __restrict__ xg2, const float* __restrict__ in2,
                   float* __restrict__ h2,
                   __nv_bfloat16* __restrict__ h2h, __nv_bfloat16* __restrict__ h2l,
                   __nv_bfloat16* __restrict__ seqh, __nv_bfloat16* __restrict__ seql) {
    int idx = blockIdx.x * 256 + threadIdx.x;
    int b = idx >> 7;
    int j = (idx & 127) * 4;
    size_t hidx = (size_t)b * HH + j;

    {
        float4 hv = *(float4*)(h2 + hidx);
        if (tgt[b * TT + t2] != 0) {
            const float* xg = xg2 + (size_t)b * H3;
            const float* in = in2 + (size_t)b * H3;
            gate4(*(const float4*)(xg + j), *(const float4*)(xg + HH + j), *(const float4*)(xg + 2*HH + j),
                  *(const float4*)(in + j), *(const float4*)(in + HH + j), *(const float4*)(in + 2*HH + j), hv);
            *(float4*)(h2 + hidx) = hv;
            store_split4(hv, h2h + hidx, h2l + hidx);
        }
        size_t so = (size_t)b * (TT * HH) + (size_t)t2 * HH + j;
        store_split4(hv, seqh + so, seql + so);   // output == state, even masked
    }
    if (t1 < TT) {
        int tok = tgt[b * TT + t1];
        if (tok != 0) {
            float4 hv = *(float4*)(h1 + hidx);
            const float* xg = proj + (size_t)tok * H3;
            const float* in = in1 + (size_t)b * H3;
            gate4(*(const float4*)(xg + j), *(const float4*)(xg + HH + j), *(const float4*)(xg + 2*HH + j),
                  *(const float4*)(in + j), *(const float4*)(in + HH + j), *(const float4*)(in + 2*HH + j), hv);
            *(float4*)(h1 + hidx) = hv;
            store_split4(hv, h1h + hidx, h1l + hidx);
        }
    }
}

// ===================== softmax over V=128 ===================================
__global__ __launch_bounds__(256)
void softmax_kernel(float* __restrict__ out) {
    int row  = blockIdx.x * 8 + (threadIdx.x >> 5);
    int lane = threadIdx.x & 31;
    float* p = out + (size_t)row * VV + lane * 4;
    float4 v = *(float4*)p;
    float m = fmaxf(fmaxf(v.x, v.y), fmaxf(v.z, v.w));
#pragma unroll
    for (int o = 16; o > 0; o >>= 1) m = fmaxf(m, __shfl_xor_sync(0xffffffffu, m, o));
    v.x = expf(v.x - m); v.y = expf(v.y - m); v.z = expf(v.z - m); v.w = expf(v.w - m);
    float s = v.x + v.y + v.z + v.w;
#pragma unroll
    for (int o = 16; o > 0; o >>= 1) s += __shfl_xor_sync(0xffffffffu, s, o);
    float inv = 1.f / s;
    v.x *= inv; v.y *= inv; v.z *= inv; v.w *= inv;
    *(float4*)p = v;
}

// ===================== launch ===============================================
static void* sym(const void* s) { void* p; cudaGetSymbolAddress(&p, s); return p; }

extern "C" void kernel_launch(void* const* d_in, const int* in_sizes, int n_in,
                              void* d_out, int out_size) {
    const int*   tgt = (const int*)  d_in[0];
    const float* enc = (const float*)d_in[1];
    const float* Wi1 = (const float*)d_in[2];
    const float* Wi2 = (const float*)d_in[3];
    const float* emb = (const float*)d_in[4];
    const float* k1  = (const float*)d_in[5];
    const float* rk1 = (const float*)d_in[6];
    const float* b1  = (const float*)d_in[7];
    const float* k2  = (const float*)d_in[8];
    const float* rk2 = (const float*)d_in[9];
    const float* b2  = (const float*)d_in[10];
    const float* Wv  = (const float*)d_in[11];
    const float* bv  = (const float*)d_in[12];
    float* out = (float*)d_out;

    float* proj = (float*)sym(g_proj);
    float* h1  = (float*)sym(g_h1);   float* h2  = (float*)sym(g_h2);
    float* in1 = (float*)sym(g_in1);  float* xg2 = (float*)sym(g_xg2);  float* in2 = (float*)sym(g_in2);
    __nv_bfloat16 *h1h=(__nv_bfloat16*)sym(g_h1h), *h1l=(__nv_bfloat16*)sym(g_h1l);
    __nv_bfloat16 *h2h=(__nv_bfloat16*)sym(g_h2h), *h2l=(__nv_bfloat16*)sym(g_h2l);
    __nv_bfloat16 *sqh=(__nv_bfloat16*)sym(g_seqh), *sql=(__nv_bfloat16*)sym(g_seql);
    __nv_bfloat16 *ench=(__nv_bfloat16*)sym(g_ench), *encl=(__nv_bfloat16*)sym(g_encl);
    __nv_bfloat16 *k1h=(__nv_bfloat16*)sym(g_k1h),   *k1l=(__nv_bfloat16*)sym(g_k1l);
    __nv_bfloat16 *rk1h=(__nv_bfloat16*)sym(g_rk1h), *rk1l=(__nv_bfloat16*)sym(g_rk1l);
    __nv_bfloat16 *k2h=(__nv_bfloat16*)sym(g_k2h),   *k2l=(__nv_bfloat16*)sym(g_k2l);
    __nv_bfloat16 *rk2h=(__nv_bfloat16*)sym(g_rk2h), *rk2l=(__nv_bfloat16*)sym(g_rk2l);
    __nv_bfloat16 *wi1h=(__nv_bfloat16*)sym(g_wi1h), *wi1l=(__nv_bfloat16*)sym(g_wi1l);
    __nv_bfloat16 *wi2h=(__nv_bfloat16*)sym(g_wi2h), *wi2l=(__nv_bfloat16*)sym(g_wi2l);
    __nv_bfloat16 *wvh=(__nv_bfloat16*)sym(g_wvh),   *wvl=(__nv_bfloat16*)sym(g_wvl);
    __nv_bfloat16 *embh=(__nv_bfloat16*)sym(g_embh), *embl=(__nv_bfloat16*)sym(g_embl);

    cudaFuncSetAttribute(tc_gemm, cudaFuncAttributeMaxDynamicSharedMemorySize, SMEM_DYN);

    dim3 blk(256);

    // ---- prep ----
    tsplit_kernel<<<dim3(HH/32, ENCC/32),blk>>>(Wi1, wi1h, wi1l, ENCC, HH);
    tsplit_kernel<<<dim3(HH/32, ENCC/32),blk>>>(Wi2, wi2h, wi2l, ENCC, HH);
    split_kernel<<<(BB*ENCC/4 + 255)/256, blk>>>(enc, ench, encl, BB*ENCC/4);
    tsplit_kernel<<<dim3(H3/32, EE/32),  blk>>>(k1,  k1h,  k1l,  EE,   H3);
    split_kernel<<<(VV*EE/4 + 255)/256,   blk>>>(emb, embh, embl, VV*EE/4);

    // h0 init: h1 = enc@Wi1, h2 = enc@Wi2 (with bf16 split outputs)
    {
        TJob a = {ench, encl, wi1h, wi1l, nullptr, h1, h1h, h1l};
        TJob b = {ench, encl, wi2h, wi2l, nullptr, h2, h2h, h2l};
        tc_gemm<<<dim3(HH/128, BB/128, 2), blk, SMEM_DYN>>>(a, b, a, ENCC, HH);
    }

    tsplit3_kernel<<<dim3(H3/32, HH/32, 3), blk>>>(rk1, rk1h, rk1l,
                                                   k2,  k2h,  k2l,
                                                   rk2, rk2h, rk2l);
    tsplit_kernel<<<dim3(VV/32, HH/32),  blk>>>(Wv,  wvh,  wvl,  HH,   VV);

    // proj = emb_table @ k1 + b1[0]  (V=128 rows only)
    {
        TJob a = {embh, embl, k1h, k1l, b1, proj, nullptr, nullptr};
        tc_gemm<<<dim3(H3/128, 1, 1), blk, SMEM_DYN>>>(a, a, a, EE, H3);
    }
    // inner1(t=0) = h1 @ rk1 + b1[1]
    {
        TJob a = {h1h, h1l, rk1h, rk1l, b1 + H3, in1, nullptr, nullptr};
        tc_gemm<<<dim3(H3/128, BB/128, 1), blk, SMEM_DYN>>>(a, a, a, HH, H3);
    }
    const int gblocks = BB * HH / 4 / 256;  // 1024
    gru_step1<<<gblocks, blk>>>(proj, tgt, 0, in1, h1, h1h, h1l);

    for (int t = 0; t < TT; t++) {
        TJob a = {h1h, h1l, k2h,  k2l,  b2,      xg2, nullptr, nullptr};
        TJob b = {h2h, h2l, rk2h, rk2l, b2 + H3, in2, nullptr, nullptr};
        TJob c = {h1h, h1l, rk1h, rk1l, b1 + H3, in1, nullptr, nullptr};
        int nz = (t == TT - 1) ? 2 : 3;   // in1 for t=TT is never consumed
        tc_gemm<<<dim3(H3/128, BB/128, nz), blk, SMEM_DYN>>>(a, b, c, HH, H3);
        gru_step_full<<<gblocks, blk>>>(proj, tgt, t + 1, in1, h1, h1h, h1l,
                                        t, xg2, in2, h2, h2h, h2l, sqh, sql);
    }

    // ---- logits = seq2 @ Wv + bv, then softmax (in d_out) ----
    {
        TJob a = {sqh, sql, wvh, wvl, bv, out, nullptr, nullptr};
        tc_gemm<<<dim3(VV/128, (BB*TT)/128, 1), blk, SMEM_DYN>>>(a, a, a, HH, VV);
    }
    softmax_kernel<<<(BB*TT)/8, blk>>>(out);
}

// round 13
// speedup vs baseline: 1.1777x; 1.0356x over previous
#include <cuda_runtime.h>
#include <cuda_bf16.h>
#include <stdint.h>
#include <math.h>

#define BB   2048
#define TT   48
#define HH   512
#define EE   256
#define VV   128
#define ENCC 1024
#define H3   1536

// ===================== stable-ISA PTX helpers (sm_80+) ======================
__device__ __forceinline__ uint32_t smem_u32(const void* p) {
    uint32_t a;
    asm("{ .reg .u64 t; cvta.to.shared.u64 t, %1; cvt.u32.u64 %0, t; }" : "=r"(a) : "l"(p));
    return a;
}
__device__ __forceinline__ void cp_async16(uint32_t dst, const void* src) {
    asm volatile("cp.async.cg.shared.global [%0], [%1], 16;" :: "r"(dst), "l"(src));
}
#define CP_COMMIT() asm volatile("cp.async.commit_group;" ::: "memory")
#define CP_WAIT1()  asm volatile("cp.async.wait_group 1;" ::: "memory")

__device__ __forceinline__ void ldsm_x4(uint32_t* r, uint32_t addr) {
    asm volatile("ldmatrix.sync.aligned.m8n8.x4.shared.b16 {%0,%1,%2,%3}, [%4];"
                 : "=r"(r[0]), "=r"(r[1]), "=r"(r[2]), "=r"(r[3]) : "r"(addr));
}
__device__ __forceinline__ void mma16816(float* d, const uint32_t* a, const uint32_t* b) {
    asm volatile("mma.sync.aligned.m16n8k16.row.col.f32.bf16.bf16.f32 "
                 "{%0,%1,%2,%3}, {%4,%5,%6,%7}, {%8,%9}, {%0,%1,%2,%3};"
                 : "+f"(d[0]), "+f"(d[1]), "+f"(d[2]), "+f"(d[3])
                 : "r"(a[0]), "r"(a[1]), "r"(a[2]), "r"(a[3]), "r"(b[0]), "r"(b[1]));
}

// ===================== device scratch (no allocations) ======================
__device__ __align__(16) float g_proj[VV * H3];
__device__ __align__(16) float g_h1 [BB * HH];
__device__ __align__(16) float g_h2 [BB * HH];
__device__ __align__(16) float g_in1[BB * H3];
__device__ __align__(16) float g_xg2[BB * H3];
__device__ __align__(16) float g_in2[BB * H3];

__device__ __align__(16) __nv_bfloat16 g_h1h[BB * HH], g_h1l[BB * HH];
__device__ __align__(16) __nv_bfloat16 g_h2h[BB * HH], g_h2l[BB * HH];
__device__ __align__(16) __nv_bfloat16 g_seqh[(size_t)BB * TT * HH], g_seql[(size_t)BB * TT * HH];
__device__ __align__(16) __nv_bfloat16 g_ench[BB * ENCC], g_encl[BB * ENCC];

__device__ __align__(16) __nv_bfloat16 g_k1h [H3 * EE],   g_k1l [H3 * EE];
__device__ __align__(16) __nv_bfloat16 g_rk1h[H3 * HH],   g_rk1l[H3 * HH];
__device__ __align__(16) __nv_bfloat16 g_k2h [H3 * HH],   g_k2l [H3 * HH];
__device__ __align__(16) __nv_bfloat16 g_rk2h[H3 * HH],   g_rk2l[H3 * HH];
__device__ __align__(16) __nv_bfloat16 g_wi1h[HH * ENCC], g_wi1l[HH * ENCC];
__device__ __align__(16) __nv_bfloat16 g_wi2h[HH * ENCC], g_wi2l[HH * ENCC];
__device__ __align__(16) __nv_bfloat16 g_wvh [VV * HH],   g_wvl [VV * HH];
__device__ __align__(16) __nv_bfloat16 g_embh[VV * EE],   g_embl[VV * EE];

__device__ __forceinline__ void split2(float v, __nv_bfloat16& h, __nv_bfloat16& l) {
    h = __float2bfloat16(v);
    l = __float2bfloat16(v - __bfloat162float(h));
}

// ===================== prep: transpose + hi/lo split ========================
__global__ __launch_bounds__(256)
void tsplit_kernel(const float* __restrict__ W, __nv_bfloat16* __restrict__ Th,
                   __nv_bfloat16* __restrict__ Tl, int K, int N) {
    __shared__ float s[32][33];
    int n0 = blockIdx.x * 32, k0 = blockIdx.y * 32;
    int tx = threadIdx.x & 31, ty = threadIdx.x >> 5;
#pragma unroll
    for (int i = 0; i < 32; i += 8)
        s[ty + i][tx] = W[(size_t)(k0 + ty + i) * N + n0 + tx];
    __syncthreads();
#pragma unroll
    for (int i = 0; i < 32; i += 8) {
        float v = s[tx][ty + i];
        __nv_bfloat16 h, l; split2(v, h, l);
        size_t o = (size_t)(n0 + ty + i) * K + k0 + tx;
        Th[o] = h; Tl[o] = l;
    }
}

__global__ __launch_bounds__(256)
void tsplit3_kernel(const float* __restrict__ W0, __nv_bfloat16* __restrict__ Th0, __nv_bfloat16* __restrict__ Tl0,
                    const float* __restrict__ W1, __nv_bfloat16* __restrict__ Th1, __nv_bfloat16* __restrict__ Tl1,
                    const float* __restrict__ W2, __nv_bfloat16* __restrict__ Th2, __nv_bfloat16* __restrict__ Tl2) {
    const float* W = (blockIdx.z == 0) ? W0 : (blockIdx.z == 1) ? W1 : W2;
    __nv_bfloat16* Th = (blockIdx.z == 0) ? Th0 : (blockIdx.z == 1) ? Th1 : Th2;
    __nv_bfloat16* Tl = (blockIdx.z == 0) ? Tl0 : (blockIdx.z == 1) ? Tl1 : Tl2;
    const int K = HH, N = H3;
    __shared__ float s[32][33];
    int n0 = blockIdx.x * 32, k0 = blockIdx.y * 32;
    int tx = threadIdx.x & 31, ty = threadIdx.x >> 5;
#pragma unroll
    for (int i = 0; i < 32; i += 8)
        s[ty + i][tx] = W[(size_t)(k0 + ty + i) * N + n0 + tx];
    __syncthreads();
#pragma unroll
    for (int i = 0; i < 32; i += 8) {
        float v = s[tx][ty + i];
        __nv_bfloat16 h, l; split2(v, h, l);
        size_t o = (size_t)(n0 + ty + i) * K + k0 + tx;
        Th[o] = h; Tl[o] = l;
    }
}

__global__ __launch_bounds__(256)
void split_kernel(const float* __restrict__ src, __nv_bfloat16* __restrict__ dh,
                  __nv_bfloat16* __restrict__ dl, int n4) {
    int i = blockIdx.x * 256 + threadIdx.x;
    if (i >= n4) return;
    float4 v = ((const float4*)src)[i];
    __nv_bfloat16 h0,l0,h1,l1,h2,l2,h3,l3;
    split2(v.x,h0,l0); split2(v.y,h1,l1); split2(v.z,h2,l2); split2(v.w,h3,l3);
    ((__nv_bfloat162*)dh)[2*i]   = __nv_bfloat162(h0,h1);
    ((__nv_bfloat162*)dh)[2*i+1] = __nv_bfloat162(h2,h3);
    ((__nv_bfloat162*)dl)[2*i]   = __nv_bfloat162(l0,l1);
    ((__nv_bfloat162*)dl)[2*i+1] = __nv_bfloat162(l2,l3);
}

// ===================== mma.sync split-bf16 GEMM =============================
// 3-stage cp.async pipeline, XOR-swizzled SMEM (64B rows, no padding),
// single __syncthreads per K-chunk.
#define TILE_B    (128 * 32 * 2)         // 8192 bytes per operand tile
#define STAGE_B   (4 * TILE_B)           // Ah, Al, Bh, Bl = 32768
#define SMEM_DYN  (3 * STAGE_B)          // 98304 bytes

#define SWOFF(r, u) ((r) * 64 + (((u) ^ (((r) >> 1) & 3)) * 16))

struct TJob {
    const __nv_bfloat16 *Ah, *Al;   // [M,K]
    const __nv_bfloat16 *Bh, *Bl;   // [N,K]
    const float* bias;
    float* C;
    __nv_bfloat16 *Ch, *Cl;
};

__global__ __launch_bounds__(256, 2)
void tc_gemm(TJob j0, TJob j1, TJob j2, int K, int N) {
    extern __shared__ __align__(16) char smem[];
    const TJob& jb = (blockIdx.z == 0) ? j0 : (blockIdx.z == 1) ? j1 : j2;
    const uint32_t sb = smem_u32(smem);
    const int tid = threadIdx.x;
    const int lane = tid & 31, warp = tid >> 5;
    const int wm = warp & 1, wn = warp >> 1;
    const int bm = blockIdx.y * 128, bn = blockIdx.x * 128;
    const int kch = K / 32;

    auto issue = [&](int c) {
        const int k0 = c * 32;
        const uint32_t st = sb + (c % 3) * STAGE_B;
#pragma unroll
        for (int i = 0; i < 8; i++) {
            const int tile = i >> 1;
            const int w = (i & 1) ? (tid + 256) & 511 : tid;
            const int row = w >> 2, u = w & 3;
            const __nv_bfloat16* src = (tile == 0) ? jb.Ah : (tile == 1) ? jb.Al
                                     : (tile == 2) ? jb.Bh : jb.Bl;
            const int roff = (tile < 2) ? bm : bn;
            cp_async16(st + tile * TILE_B + SWOFF(row, u),
                       src + (size_t)(roff + row) * K + k0 + u * 8);
        }
    };

    float acc[4][4][4];
#pragma unroll
    for (int i = 0; i < 4; i++)
#pragma unroll
        for (int j = 0; j < 4; j++)
#pragma unroll
            for (int q = 0; q < 4; q++) acc[i][j][q] = 0.f;

    const int arow = lane & 15, au = (lane >> 4);
    const int brow4 = lane & 7;
    const int bu = (lane >> 3) & 1;
    const int bnsel = ((lane >> 4) & 1) * 8;

    issue(0); CP_COMMIT();
    issue(1); CP_COMMIT();

    for (int c = 0; c < kch; c++) {
        CP_WAIT1();
        __syncthreads();
        if (c + 2 < kch) issue(c + 2);
        CP_COMMIT();

        const uint32_t st = sb + (c % 3) * STAGE_B;
        const uint32_t ah = st,              al = st + TILE_B;
        const uint32_t bh = st + 2 * TILE_B, bl = st + 3 * TILE_B;
#pragma unroll
        for (int kt = 0; kt < 2; kt++) {
            uint32_t afh[4][4], bfh[2][4], bfl[2][4];
#pragma unroll
            for (int mt = 0; mt < 4; mt++) {
                int r = wm * 64 + mt * 16 + arow;
                ldsm_x4(afh[mt], ah + SWOFF(r, kt * 2 + au));
            }
#pragma unroll
            for (int p = 0; p < 2; p++) {
                int r = wn * 32 + p * 16 + bnsel + brow4;
                ldsm_x4(bfh[p], bh + SWOFF(r, kt * 2 + bu));
                ldsm_x4(bfl[p], bl + SWOFF(r, kt * 2 + bu));
            }
#pragma unroll
            for (int mt = 0; mt < 4; mt++)
#pragma unroll
                for (int nt = 0; nt < 4; nt++) {
                    mma16816(acc[mt][nt], afh[mt], &bfh[nt >> 1][(nt & 1) * 2]);
                    mma16816(acc[mt][nt], afh[mt], &bfl[nt >> 1][(nt & 1) * 2]);
                }
            uint32_t afl[4][4];
#pragma unroll
            for (int mt = 0; mt < 4; mt++) {
                int r = wm * 64 + mt * 16 + arow;
                ldsm_x4(afl[mt], al + SWOFF(r, kt * 2 + au));
            }
#pragma unroll
            for (int mt = 0; mt < 4; mt++)
#pragma unroll
                for (int nt = 0; nt < 4; nt++)
                    mma16816(acc[mt][nt], afl[mt], &bfh[nt >> 1][(nt & 1) * 2]);
        }
    }

    const int quad = lane >> 2, pair = lane & 3;
#pragma unroll
    for (int mt = 0; mt < 4; mt++) {
#pragma unroll
        for (int h = 0; h < 2; h++) {
            int row = bm + wm * 64 + mt * 16 + quad + h * 8;
            float* crow = jb.C + (size_t)row * N;
#pragma unroll
            for (int nt = 0; nt < 4; nt++) {
                int col = bn + wn * 32 + nt * 8 + pair * 2;
                float v0 = acc[mt][nt][2 * h]     + (jb.bias ? jb.bias[col]     : 0.f);
                float v1 = acc[mt][nt][2 * h + 1] + (jb.bias ? jb.bias[col + 1] : 0.f);
                *(float2*)(crow + col) = make_float2(v0, v1);
                if (jb.Ch) {
                    __nv_bfloat16 h0, l0, h1, l1;
                    split2(v0, h0, l0); split2(v1, h1, l1);
                    *(__nv_bfloat162*)(jb.Ch + (size_t)row * N + col) = __nv_bfloat162(h0, h1);
                    *(__nv_bfloat162*)(jb.Cl + (size_t)row * N + col) = __nv_bfloat162(l0, l1);
                }
            }
        }
    }
}

// ===================== GRU gate updates =====================================
__device__ __forceinline__ float sigm_(float x) { return 1.f / (1.f + expf(-x)); }

__device__ __forceinline__ void gate4(const float4& xz, const float4& xr, const float4& xh,
                                      const float4& rz, const float4& rr, const float4& rh,
                                      float4& hv) {
    float z, r, hg;
    z = sigm_(xz.x + rz.x); r = sigm_(xr.x + rr.x); hg = tanhf(xh.x + r * rh.x); hv.x = z * hv.x + (1.f - z) * hg;
    z = sigm_(xz.y + rz.y); r = sigm_(xr.y + rr.y); hg = tanhf(xh.y + r * rh.y); hv.y = z * hv.y + (1.f - z) * hg;
    z = sigm_(xz.z + rz.z); r = sigm_(xr.z + rr.z); hg = tanhf(xh.z + r * rh.z); hv.z = z * hv.z + (1.f - z) * hg;
    z = sigm_(xz.w + rz.w); r = sigm_(xr.w + rr.w); hg = tanhf(xh.w + r * rh.w); hv.w = z * hv.w + (1.f - z) * hg;
}
__device__ __forceinline__ void store_split4(const float4& hv, __nv_bfloat16* ph, __nv_bfloat16* pl) {
    __nv_bfloat16 a0,b0,a1,b1,a2,b2,a3,b3;
    split2(hv.x,a0,b0); split2(hv.y,a1,b1); split2(hv.z,a2,b2); split2(hv.w,a3,b3);
    *(__nv_bfloat162*)(ph)     = __nv_bfloat162(a0,a1);
    *(__nv_bfloat162*)(ph + 2) = __nv_bfloat162(a2,a3);
    *(__nv_bfloat162*)(pl)     = __nv_bfloat162(b0,b1);
    *(__nv_bfloat162*)(pl + 2) = __nv_bfloat162(b2,b3);
}

// layer-1 update at time t1
__global__ __launch_bounds__(256)
void gru_step1(const float* __restrict__ proj, const int* __restrict__ tgt, int t1,
               const float* __restrict__ in1, float* __restrict__ h1,
               __nv_bfloat16* __restrict__ h1h, __nv_bfloat16* __restrict__ h1l) {
    int idx = blockIdx.x * 256 + threadIdx.x;
    int b = idx >> 7;
    int j = (idx & 127) * 4;
    size_t hidx = (size_t)b * HH + j;
    int tok = tgt[b * TT + t1];
    if (tok != 0) {
        float4 hv = *(float4*)(h1 + hidx);
        const float* xg = proj + (size_t)tok * H3;
        const float* in = in1 + (size_t)b * H3;
        gate4(*(const float4*)(xg + j), *(const float4*)(xg + HH + j), *(const float4*)(xg + 2*HH + j),
              *(const float4*)(in + j), *(const float4*)(in + HH + j), *(const float4*)(in + 2*HH + j), hv);
        *(float4*)(h1 + hidx) = hv;
        store_split4(hv, h1h + hidx, h1l + hidx);
    }
}

// layer-2 update at time t2 + seq emit
__global__ __launch_bounds__(256)
void gru_step2(const int* __restrict__ tgt, int t2,
               const float* __restrict__ xg2, const float* __restrict__ in2,
               float* __restrict__ h2,
               __nv_bfloat16* __restrict__ h2h, __nv_bfloat16* __restrict__ h2l,
               __nv_bfloat16* __restrict__ seqh, __nv_bfloat16* __restrict__ seql) {
    int idx = blockIdx.x * 256 + threadIdx.x;
    int b = idx >> 7;
    int j = (idx & 127) * 4;
    size_t hidx = (size_t)b * HH + j;

    float4 hv = *(float4*)(h2 + hidx);
    if (tgt[b * TT + t2] != 0) {
        const float* xg = xg2 + (size_t)b * H3;
        const float* in = in2 + (size_t)b * H3;
        gate4(*(const float4*)(xg + j), *(const float4*)(xg + HH + j), *(const float4*)(xg + 2*HH + j),
              *(const float4*)(in + j), *(const float4*)(in + HH + j), *(const float4*)(in + 2*HH + j), hv);
        *(float4*)(h2 + hidx) = hv;
        store_split4(hv, h2h + hidx, h2l + hidx);
    }
    size_t so = (size_t)b * (TT * HH) + (size_t)t2 * HH + j;
    store_split4(hv, seqh + so, seql + so);   // output == state, even masked
}

// ===================== softmax over V=128 ===================================
__global__ __launch_bounds__(256)
void softmax_kernel(float* __restrict__ out) {
    int row  = blockIdx.x * 8 + (threadIdx.x >> 5);
    int lane = threadIdx.x & 31;
    float* p = out + (size_t)row * VV + lane * 4;
    float4 v = *(float4*)p;
    float m = fmaxf(fmaxf(v.x, v.y), fmaxf(v.z, v.w));
#pragma unroll
    for (int o = 16; o > 0; o >>= 1) m = fmaxf(m, __shfl_xor_sync(0xffffffffu, m, o));
    v.x = expf(v.x - m); v.y = expf(v.y - m); v.z = expf(v.z - m); v.w = expf(v.w - m);
    float s = v.x + v.y + v.z + v.w;
#pragma unroll
    for (int o = 16; o > 0; o >>= 1) s += __shfl_xor_sync(0xffffffffu, s, o);
    float inv = 1.f / s;
    v.x *= inv; v.y *= inv; v.z *= inv; v.w *= inv;
    *(float4*)p = v;
}

// ===================== launch ===============================================
static void* sym(const void* s) { void* p; cudaGetSymbolAddress(&p, s); return p; }

extern "C" void kernel_launch(void* const* d_in, const int* in_sizes, int n_in,
                              void* d_out, int out_size) {
    const int*   tgt = (const int*)  d_in[0];
    const float* enc = (const float*)d_in[1];
    const float* Wi1 = (const float*)d_in[2];
    const float* Wi2 = (const float*)d_in[3];
    const float* emb = (const float*)d_in[4];
    const float* k1  = (const float*)d_in[5];
    const float* rk1 = (const float*)d_in[6];
    const float* b1  = (const float*)d_in[7];
    const float* k2  = (const float*)d_in[8];
    const float* rk2 = (const float*)d_in[9];
    const float* b2  = (const float*)d_in[10];
    const float* Wv  = (const float*)d_in[11];
    const float* bv  = (const float*)d_in[12];
    float* out = (float*)d_out;

    float* proj = (float*)sym(g_proj);
    float* h1  = (float*)sym(g_h1);   float* h2  = (float*)sym(g_h2);
    float* in1 = (float*)sym(g_in1);  float* xg2 = (float*)sym(g_xg2);  float* in2 = (float*)sym(g_in2);
    __nv_bfloat16 *h1h=(__nv_bfloat16*)sym(g_h1h), *h1l=(__nv_bfloat16*)sym(g_h1l);
    __nv_bfloat16 *h2h=(__nv_bfloat16*)sym(g_h2h), *h2l=(__nv_bfloat16*)sym(g_h2l);
    __nv_bfloat16 *sqh=(__nv_bfloat16*)sym(g_seqh), *sql=(__nv_bfloat16*)sym(g_seql);
    __nv_bfloat16 *ench=(__nv_bfloat16*)sym(g_ench), *encl=(__nv_bfloat16*)sym(g_encl);
    __nv_bfloat16 *k1h=(__nv_bfloat16*)sym(g_k1h),   *k1l=(__nv_bfloat16*)sym(g_k1l);
    __nv_bfloat16 *rk1h=(__nv_bfloat16*)sym(g_rk1h), *rk1l=(__nv_bfloat16*)sym(g_rk1l);
    __nv_bfloat16 *k2h=(__nv_bfloat16*)sym(g_k2h),   *k2l=(__nv_bfloat16*)sym(g_k2l);
    __nv_bfloat16 *rk2h=(__nv_bfloat16*)sym(g_rk2h), *rk2l=(__nv_bfloat16*)sym(g_rk2l);
    __nv_bfloat16 *wi1h=(__nv_bfloat16*)sym(g_wi1h), *wi1l=(__nv_bfloat16*)sym(g_wi1l);
    __nv_bfloat16 *wi2h=(__nv_bfloat16*)sym(g_wi2h), *wi2l=(__nv_bfloat16*)sym(g_wi2l);
    __nv_bfloat16 *wvh=(__nv_bfloat16*)sym(g_wvh),   *wvl=(__nv_bfloat16*)sym(g_wvl);
    __nv_bfloat16 *embh=(__nv_bfloat16*)sym(g_embh), *embl=(__nv_bfloat16*)sym(g_embl);

    cudaFuncSetAttribute(tc_gemm, cudaFuncAttributeMaxDynamicSharedMemorySize, SMEM_DYN);

    // side stream + events for fork-join capture (created per call; leaked —
    // kernel_launch runs only a handful of times, replays reuse the graph)
    cudaStream_t sB;
    cudaStreamCreateWithFlags(&sB, cudaStreamNonBlocking);
    cudaEvent_t evFork, evA, evB, evJ;
    cudaEventCreateWithFlags(&evFork, cudaEventDisableTiming);
    cudaEventCreateWithFlags(&evA,    cudaEventDisableTiming);
    cudaEventCreateWithFlags(&evB,    cudaEventDisableTiming);
    cudaEventCreateWithFlags(&evJ,    cudaEventDisableTiming);

    dim3 blk(256);

    // ---- prep (stream 0) ----
    tsplit_kernel<<<dim3(HH/32, ENCC/32),blk>>>(Wi1, wi1h, wi1l, ENCC, HH);
    tsplit_kernel<<<dim3(HH/32, ENCC/32),blk>>>(Wi2, wi2h, wi2l, ENCC, HH);
    split_kernel<<<(BB*ENCC/4 + 255)/256, blk>>>(enc, ench, encl, BB*ENCC/4);
    tsplit_kernel<<<dim3(H3/32, EE/32),  blk>>>(k1,  k1h,  k1l,  EE,   H3);
    split_kernel<<<(VV*EE/4 + 255)/256,   blk>>>(emb, embh, embl, VV*EE/4);

    {
        TJob a = {ench, encl, wi1h, wi1l, nullptr, h1, h1h, h1l};
        TJob b = {ench, encl, wi2h, wi2l, nullptr, h2, h2h, h2l};
        tc_gemm<<<dim3(HH/128, BB/128, 2), blk, SMEM_DYN>>>(a, b, a, ENCC, HH);
    }
    tsplit3_kernel<<<dim3(H3/32, HH/32, 3), blk>>>(rk1, rk1h, rk1l,
                                                   k2,  k2h,  k2l,
                                                   rk2, rk2h, rk2l);
    tsplit_kernel<<<dim3(VV/32, HH/32),  blk>>>(Wv,  wvh,  wvl,  HH,   VV);
    {
        TJob a = {embh, embl, k1h, k1l, b1, proj, nullptr, nullptr};
        tc_gemm<<<dim3(H3/128, 1, 1), blk, SMEM_DYN>>>(a, a, a, EE, H3);
    }
    {
        TJob a = {h1h, h1l, rk1h, rk1l, b1 + H3, in1, nullptr, nullptr};
        tc_gemm<<<dim3(H3/128, BB/128, 1), blk, SMEM_DYN>>>(a, a, a, HH, H3);
    }
    const int gblocks = BB * HH / 4 / 256;  // 1024
    gru_step1<<<gblocks, blk>>>(proj, tgt, 0, in1, h1, h1h, h1l);

    // ---- fork: sB joins the capture graph after the prologue ----
    cudaEventRecord(evFork, 0);
    cudaStreamWaitEvent(sB, evFork, 0);

    for (int t = 0; t < TT; t++) {
        // stream0 must see h1(t) from gru1 on sB (recorded end of iter t-1)
        if (t > 0) cudaStreamWaitEvent(0, evA, 0);

        // branch A (stream0): jobs 0+1 -> layer-2 gate update
        {
            TJob a = {h1h, h1l, k2h,  k2l,  b2,      xg2, nullptr, nullptr};
            TJob b = {h2h, h2l, rk2h, rk2l, b2 + H3, in2, nullptr, nullptr};
            tc_gemm<<<dim3(H3/128, BB/128, 2), blk, SMEM_DYN>>>(a, b, a, HH, H3);
        }
        cudaEventRecord(evB, 0);             // after L01: h1h reads complete
        gru_step2<<<gblocks, blk>>>(tgt, t, xg2, in2, h2, h2h, h2l, sqh, sql);

        // branch B (sB): job c -> layer-1 gate update for t+1
        if (t + 1 < TT) {
            TJob c = {h1h, h1l, rk1h, rk1l, b1 + H3, in1, nullptr, nullptr};
            tc_gemm<<<dim3(H3/128, BB/128, 1), blk, SMEM_DYN, sB>>>(c, c, c, HH, H3);
            cudaStreamWaitEvent(sB, evB, 0); // gru1 writes h1h only after L01 read it
            gru_step1<<<gblocks, blk, 0, sB>>>(proj, tgt, t + 1, in1, h1, h1h, h1l);
            cudaEventRecord(evA, sB);
        }
    }

    // ---- join sB back into stream0 before epilogue ----
    cudaEventRecord(evJ, sB);
    cudaStreamWaitEvent(0, evJ, 0);

    // ---- logits = seq2 @ Wv + bv, then softmax (in d_out) ----
    {
        TJob a = {sqh, sql, wvh, wvl, bv, out, nullptr, nullptr};
        tc_gemm<<<dim3(VV/128, (BB*TT)/128, 1), blk, SMEM_DYN>>>(a, a, a, HH, VV);
    }
    softmax_kernel<<<(BB*TT)/8, blk>>>(out);
}

// round 14
// speedup vs baseline: 1.5287x; 1.2980x over previous
#include <cuda_runtime.h>
#include <cuda_fp16.h>
#include <stdint.h>
#include <math.h>

#define BB   2048
#define TT   48
#define HH   512
#define EE   256
#define VV   128
#define ENCC 1024
#define H3   1536

// ===================== stable-ISA PTX helpers (sm_80+) ======================
__device__ __forceinline__ uint32_t smem_u32(const void* p) {
    uint32_t a;
    asm("{ .reg .u64 t; cvta.to.shared.u64 t, %1; cvt.u32.u64 %0, t; }" : "=r"(a) : "l"(p));
    return a;
}
__device__ __forceinline__ void cp_async16(uint32_t dst, const void* src) {
    asm volatile("cp.async.cg.shared.global [%0], [%1], 16;" :: "r"(dst), "l"(src));
}
#define CP_COMMIT() asm volatile("cp.async.commit_group;" ::: "memory")
#define CP_WAIT1()  asm volatile("cp.async.wait_group 1;" ::: "memory")

__device__ __forceinline__ void ldsm_x4(uint32_t* r, uint32_t addr) {
    asm volatile("ldmatrix.sync.aligned.m8n8.x4.shared.b16 {%0,%1,%2,%3}, [%4];"
                 : "=r"(r[0]), "=r"(r[1]), "=r"(r[2]), "=r"(r[3]) : "r"(addr));
}
__device__ __forceinline__ void mma16816(float* d, const uint32_t* a, const uint32_t* b) {
    asm volatile("mma.sync.aligned.m16n8k16.row.col.f32.f16.f16.f32 "
                 "{%0,%1,%2,%3}, {%4,%5,%6,%7}, {%8,%9}, {%0,%1,%2,%3};"
                 : "+f"(d[0]), "+f"(d[1]), "+f"(d[2]), "+f"(d[3])
                 : "r"(a[0]), "r"(a[1]), "r"(a[2]), "r"(a[3]), "r"(b[0]), "r"(b[1]));
}

// ===================== device scratch (no allocations) ======================
__device__ __align__(16) float g_proj[VV * H3];
__device__ __align__(16) float g_h1 [BB * HH];
__device__ __align__(16) float g_h2 [BB * HH];
__device__ __align__(16) float g_in1[BB * H3];
__device__ __align__(16) float g_xg2[BB * H3];
__device__ __align__(16) float g_in2[BB * H3];

// activations: fp16 hi/lo (A operands)
__device__ __align__(16) __half g_h1h[BB * HH], g_h1l[BB * HH];
__device__ __align__(16) __half g_h2h[BB * HH], g_h2l[BB * HH];
__device__ __align__(16) __half g_seqh[(size_t)BB * TT * HH], g_seql[(size_t)BB * TT * HH];
__device__ __align__(16) __half g_ench[BB * ENCC], g_encl[BB * ENCC];
__device__ __align__(16) __half g_embh[VV * EE],   g_embl[VV * EE];

// weights: fp16 hi only, transposed [N,K] (B operands)
__device__ __align__(16) __half g_k1h [H3 * EE];
__device__ __align__(16) __half g_rk1h[H3 * HH];
__device__ __align__(16) __half g_k2h [H3 * HH];
__device__ __align__(16) __half g_rk2h[H3 * HH];
__device__ __align__(16) __half g_wi1h[HH * ENCC];
__device__ __align__(16) __half g_wi2h[HH * ENCC];
__device__ __align__(16) __half g_wvh [VV * HH];

__device__ __forceinline__ void split2(float v, __half& h, __half& l) {
    h = __float2half(v);
    l = __float2half(v - __half2float(h));
}

// ===================== prep: transpose (hi only) ============================
__global__ __launch_bounds__(256)
void tsplit_kernel(const float* __restrict__ W, __half* __restrict__ Th, int K, int N) {
    __shared__ float s[32][33];
    int n0 = blockIdx.x * 32, k0 = blockIdx.y * 32;
    int tx = threadIdx.x & 31, ty = threadIdx.x >> 5;
#pragma unroll
    for (int i = 0; i < 32; i += 8)
        s[ty + i][tx] = W[(size_t)(k0 + ty + i) * N + n0 + tx];
    __syncthreads();
#pragma unroll
    for (int i = 0; i < 32; i += 8)
        Th[(size_t)(n0 + ty + i) * K + k0 + tx] = __float2half(s[tx][ty + i]);
}

__global__ __launch_bounds__(256)
void tsplit3_kernel(const float* __restrict__ W0, __half* __restrict__ Th0,
                    const float* __restrict__ W1, __half* __restrict__ Th1,
                    const float* __restrict__ W2, __half* __restrict__ Th2) {
    const float* W = (blockIdx.z == 0) ? W0 : (blockIdx.z == 1) ? W1 : W2;
    __half* Th = (blockIdx.z == 0) ? Th0 : (blockIdx.z == 1) ? Th1 : Th2;
    const int K = HH, N = H3;
    __shared__ float s[32][33];
    int n0 = blockIdx.x * 32, k0 = blockIdx.y * 32;
    int tx = threadIdx.x & 31, ty = threadIdx.x >> 5;
#pragma unroll
    for (int i = 0; i < 32; i += 8)
        s[ty + i][tx] = W[(size_t)(k0 + ty + i) * N + n0 + tx];
    __syncthreads();
#pragma unroll
    for (int i = 0; i < 32; i += 8)
        Th[(size_t)(n0 + ty + i) * K + k0 + tx] = __float2half(s[tx][ty + i]);
}

__global__ __launch_bounds__(256)
void split_kernel(const float* __restrict__ src, __half* __restrict__ dh,
                  __half* __restrict__ dl, int n4) {
    int i = blockIdx.x * 256 + threadIdx.x;
    if (i >= n4) return;
    float4 v = ((const float4*)src)[i];
    __half h0,l0,h1,l1,h2,l2,h3,l3;
    split2(v.x,h0,l0); split2(v.y,h1,l1); split2(v.z,h2,l2); split2(v.w,h3,l3);
    ((__half2*)dh)[2*i]   = __halves2half2(h0,h1);
    ((__half2*)dh)[2*i+1] = __halves2half2(h2,h3);
    ((__half2*)dl)[2*i]   = __halves2half2(l0,l1);
    ((__half2*)dl)[2*i+1] = __halves2half2(l2,l3);
}

// ===================== mma.sync 2-pass fp16 GEMM ============================
// C = (Ah + Al) @ Bh^T: activations split hi/lo fp16, weights fp16 hi.
// 3-stage cp.async pipeline, XOR-swizzled SMEM (64B rows), one sync/chunk.
#define TILE_B    (128 * 32 * 2)         // 8192 bytes per operand tile
#define STAGE_B   (3 * TILE_B)           // Ah, Al, Bh = 24576
#define SMEM_DYN  (3 * STAGE_B)          // 73728 bytes

#define SWOFF(r, u) ((r) * 64 + (((u) ^ (((r) >> 1) & 3)) * 16))

struct TJob {
    const __half *Ah, *Al;   // [M,K]
    const __half *Bh;        // [N,K]
    const float* bias;
    float* C;
    __half *Ch, *Cl;
};

__global__ __launch_bounds__(256, 2)
void tc_gemm(TJob j0, TJob j1, TJob j2, int K, int N) {
    extern __shared__ __align__(16) char smem[];
    const TJob& jb = (blockIdx.z == 0) ? j0 : (blockIdx.z == 1) ? j1 : j2;
    const uint32_t sb = smem_u32(smem);
    const int tid = threadIdx.x;
    const int lane = tid & 31, warp = tid >> 5;
    const int wm = warp & 1, wn = warp >> 1;
    const int bm = blockIdx.y * 128, bn = blockIdx.x * 128;
    const int kch = K / 32;

    auto issue = [&](int c) {
        const int k0 = c * 32;
        const uint32_t st = sb + (c % 3) * STAGE_B;
#pragma unroll
        for (int i = 0; i < 6; i++) {
            const int tile = i >> 1;
            const int w = (i & 1) ? (tid + 256) & 511 : tid;
            const int row = w >> 2, u = w & 3;
            const __half* src = (tile == 0) ? jb.Ah : (tile == 1) ? jb.Al : jb.Bh;
            const int roff = (tile < 2) ? bm : bn;
            cp_async16(st + tile * TILE_B + SWOFF(row, u),
                       src + (size_t)(roff + row) * K + k0 + u * 8);
        }
    };

    float acc[4][4][4];
#pragma unroll
    for (int i = 0; i < 4; i++)
#pragma unroll
        for (int j = 0; j < 4; j++)
#pragma unroll
            for (int q = 0; q < 4; q++) acc[i][j][q] = 0.f;

    const int arow = lane & 15, au = (lane >> 4);
    const int brow4 = lane & 7;
    const int bu = (lane >> 3) & 1;
    const int bnsel = ((lane >> 4) & 1) * 8;

    issue(0); CP_COMMIT();
    issue(1); CP_COMMIT();

    for (int c = 0; c < kch; c++) {
        CP_WAIT1();
        __syncthreads();
        if (c + 2 < kch) issue(c + 2);
        CP_COMMIT();

        const uint32_t st = sb + (c % 3) * STAGE_B;
        const uint32_t ah = st, al = st + TILE_B, bh = st + 2 * TILE_B;
#pragma unroll
        for (int kt = 0; kt < 2; kt++) {
            uint32_t afh[4][4], bfh[2][4];
#pragma unroll
            for (int mt = 0; mt < 4; mt++) {
                int r = wm * 64 + mt * 16 + arow;
                ldsm_x4(afh[mt], ah + SWOFF(r, kt * 2 + au));
            }
#pragma unroll
            for (int p = 0; p < 2; p++) {
                int r = wn * 32 + p * 16 + bnsel + brow4;
                ldsm_x4(bfh[p], bh + SWOFF(r, kt * 2 + bu));
            }
#pragma unroll
            for (int mt = 0; mt < 4; mt++)
#pragma unroll
                for (int nt = 0; nt < 4; nt++)
                    mma16816(acc[mt][nt], afh[mt], &bfh[nt >> 1][(nt & 1) * 2]);
            uint32_t afl[4][4];
#pragma unroll
            for (int mt = 0; mt < 4; mt++) {
                int r = wm * 64 + mt * 16 + arow;
                ldsm_x4(afl[mt], al + SWOFF(r, kt * 2 + au));
            }
#pragma unroll
            for (int mt = 0; mt < 4; mt++)
#pragma unroll
                for (int nt = 0; nt < 4; nt++)
                    mma16816(acc[mt][nt], afl[mt], &bfh[nt >> 1][(nt & 1) * 2]);
        }
    }

    const int quad = lane >> 2, pair = lane & 3;
#pragma unroll
    for (int mt = 0; mt < 4; mt++) {
#pragma unroll
        for (int h = 0; h < 2; h++) {
            int row = bm + wm * 64 + mt * 16 + quad + h * 8;
            float* crow = jb.C + (size_t)row * N;
#pragma unroll
            for (int nt = 0; nt < 4; nt++) {
                int col = bn + wn * 32 + nt * 8 + pair * 2;
                float v0 = acc[mt][nt][2 * h]     + (jb.bias ? jb.bias[col]     : 0.f);
                float v1 = acc[mt][nt][2 * h + 1] + (jb.bias ? jb.bias[col + 1] : 0.f);
                *(float2*)(crow + col) = make_float2(v0, v1);
                if (jb.Ch) {
                    __half h0, l0, h1, l1;
                    split2(v0, h0, l0); split2(v1, h1, l1);
                    *(__half2*)(jb.Ch + (size_t)row * N + col) = __halves2half2(h0, h1);
                    *(__half2*)(jb.Cl + (size_t)row * N + col) = __halves2half2(l0, l1);
                }
            }
        }
    }
}

// ===================== GRU gate updates =====================================
__device__ __forceinline__ float sigm_(float x) { return 1.f / (1.f + expf(-x)); }

__device__ __forceinline__ void gate4(const float4& xz, const float4& xr, const float4& xh,
                                      const float4& rz, const float4& rr, const float4& rh,
                                      float4& hv) {
    float z, r, hg;
    z = sigm_(xz.x + rz.x); r = sigm_(xr.x + rr.x); hg = tanhf(xh.x + r * rh.x); hv.x = z * hv.x + (1.f - z) * hg;
    z = sigm_(xz.y + rz.y); r = sigm_(xr.y + rr.y); hg = tanhf(xh.y + r * rh.y); hv.y = z * hv.y + (1.f - z) * hg;
    z = sigm_(xz.z + rz.z); r = sigm_(xr.z + rr.z); hg = tanhf(xh.z + r * rh.z); hv.z = z * hv.z + (1.f - z) * hg;
    z = sigm_(xz.w + rz.w); r = sigm_(xr.w + rr.w); hg = tanhf(xh.w + r * rh.w); hv.w = z * hv.w + (1.f - z) * hg;
}
__device__ __forceinline__ void store_split4(const float4& hv, __half* ph, __half* pl) {
    __half a0,b0,a1,b1,a2,b2,a3,b3;
    split2(hv.x,a0,b0); split2(hv.y,a1,b1); split2(hv.z,a2,b2); split2(hv.w,a3,b3);
    *(__half2*)(ph)     = __halves2half2(a0,a1);
    *(__half2*)(ph + 2) = __halves2half2(a2,a3);
    *(__half2*)(pl)     = __halves2half2(b0,b1);
    *(__half2*)(pl + 2) = __halves2half2(b2,b3);
}

// layer-1 update at time t1
__global__ __launch_bounds__(256)
void gru_step1(const float* __restrict__ proj, const int* __restrict__ tgt, int t1,
               const float* __restrict__ in1, float* __restrict__ h1,
               __half* __restrict__ h1h, __half* __restrict__ h1l) {
    int idx = blockIdx.x * 256 + threadIdx.x;
    int b = idx >> 7;
    int j = (idx & 127) * 4;
    size_t hidx = (size_t)b * HH + j;
    int tok = tgt[b * TT + t1];
    if (tok != 0) {
        float4 hv = *(float4*)(h1 + hidx);
        const float* xg = proj + (size_t)tok * H3;
        const float* in = in1 + (size_t)b * H3;
        gate4(*(const float4*)(xg + j), *(const float4*)(xg + HH + j), *(const float4*)(xg + 2*HH + j),
              *(const float4*)(in + j), *(const float4*)(in + HH + j), *(const float4*)(in + 2*HH + j), hv);
        *(float4*)(h1 + hidx) = hv;
        store_split4(hv, h1h + hidx, h1l + hidx);
    }
}

// layer-2 update at time t2 + seq emit
__global__ __launch_bounds__(256)
void gru_step2(const int* __restrict__ tgt, int t2,
               const float* __restrict__ xg2, const float* __restrict__ in2,
               float* __restrict__ h2,
               __half* __restrict__ h2h, __half* __restrict__ h2l,
               __half* __restrict__ seqh, __half* __restrict__ seql) {
    int idx = blockIdx.x * 256 + threadIdx.x;
    int b = idx >> 7;
    int j = (idx & 127) * 4;
    size_t hidx = (size_t)b * HH + j;

    float4 hv = *(float4*)(h2 + hidx);
    if (tgt[b * TT + t2] != 0) {
        const float* xg = xg2 + (size_t)b * H3;
        const float* in = in2 + (size_t)b * H3;
        gate4(*(const float4*)(xg + j), *(const float4*)(xg + HH + j), *(const float4*)(xg + 2*HH + j),
              *(const float4*)(in + j), *(const float4*)(in + HH + j), *(const float4*)(in + 2*HH + j), hv);
        *(float4*)(h2 + hidx) = hv;
        store_split4(hv, h2h + hidx, h2l + hidx);
    }
    size_t so = (size_t)b * (TT * HH) + (size_t)t2 * HH + j;
    store_split4(hv, seqh + so, seql + so);   // output == state, even masked
}

// ===================== softmax over V=128 ===================================
__global__ __launch_bounds__(256)
void softmax_kernel(float* __restrict__ out) {
    int row  = blockIdx.x * 8 + (threadIdx.x >> 5);
    int lane = threadIdx.x & 31;
    float* p = out + (size_t)row * VV + lane * 4;
    float4 v = *(float4*)p;
    float m = fmaxf(fmaxf(v.x, v.y), fmaxf(v.z, v.w));
#pragma unroll
    for (int o = 16; o > 0; o >>= 1) m = fmaxf(m, __shfl_xor_sync(0xffffffffu, m, o));
    v.x = expf(v.x - m); v.y = expf(v.y - m); v.z = expf(v.z - m); v.w = expf(v.w - m);
    float s = v.x + v.y + v.z + v.w;
#pragma unroll
    for (int o = 16; o > 0; o >>= 1) s += __shfl_xor_sync(0xffffffffu, s, o);
    float inv = 1.f / s;
    v.x *= inv; v.y *= inv; v.z *= inv; v.w *= inv;
    *(float4*)p = v;
}

// ===================== launch ===============================================
static void* sym(const void* s) { void* p; cudaGetSymbolAddress(&p, s); return p; }

extern "C" void kernel_launch(void* const* d_in, const int* in_sizes, int n_in,
                              void* d_out, int out_size) {
    const int*   tgt = (const int*)  d_in[0];
    const float* enc = (const float*)d_in[1];
    const float* Wi1 = (const float*)d_in[2];
    const float* Wi2 = (const float*)d_in[3];
    const float* emb = (const float*)d_in[4];
    const float* k1  = (const float*)d_in[5];
    const float* rk1 = (const float*)d_in[6];
    const float* b1  = (const float*)d_in[7];
    const float* k2  = (const float*)d_in[8];
    const float* rk2 = (const float*)d_in[9];
    const float* b2  = (const float*)d_in[10];
    const float* Wv  = (const float*)d_in[11];
    const float* bv  = (const float*)d_in[12];
    float* out = (float*)d_out;

    float* proj = (float*)sym(g_proj);
    float* h1  = (float*)sym(g_h1);   float* h2  = (float*)sym(g_h2);
    float* in1 = (float*)sym(g_in1);  float* xg2 = (float*)sym(g_xg2);  float* in2 = (float*)sym(g_in2);
    __half *h1h=(__half*)sym(g_h1h), *h1l=(__half*)sym(g_h1l);
    __half *h2h=(__half*)sym(g_h2h), *h2l=(__half*)sym(g_h2l);
    __half *sqh=(__half*)sym(g_seqh), *sql=(__half*)sym(g_seql);
    __half *ench=(__half*)sym(g_ench), *encl=(__half*)sym(g_encl);
    __half *embh=(__half*)sym(g_embh), *embl=(__half*)sym(g_embl);
    __half *k1h=(__half*)sym(g_k1h);
    __half *rk1h=(__half*)sym(g_rk1h);
    __half *k2h=(__half*)sym(g_k2h);
    __half *rk2h=(__half*)sym(g_rk2h);
    __half *wi1h=(__half*)sym(g_wi1h);
    __half *wi2h=(__half*)sym(g_wi2h);
    __half *wvh=(__half*)sym(g_wvh);

    cudaFuncSetAttribute(tc_gemm, cudaFuncAttributeMaxDynamicSharedMemorySize, SMEM_DYN);

    // side stream + events for fork-join capture (created per call; leaked)
    cudaStream_t sB;
    cudaStreamCreateWithFlags(&sB, cudaStreamNonBlocking);
    cudaEvent_t evFork, evA, evB, evJ;
    cudaEventCreateWithFlags(&evFork, cudaEventDisableTiming);
    cudaEventCreateWithFlags(&evA,    cudaEventDisableTiming);
    cudaEventCreateWithFlags(&evB,    cudaEventDisableTiming);
    cudaEventCreateWithFlags(&evJ,    cudaEventDisableTiming);

    dim3 blk(256);

    // ---- prep (stream 0) ----
    tsplit_kernel<<<dim3(HH/32, ENCC/32),blk>>>(Wi1, wi1h, ENCC, HH);
    tsplit_kernel<<<dim3(HH/32, ENCC/32),blk>>>(Wi2, wi2h, ENCC, HH);
    split_kernel<<<(BB*ENCC/4 + 255)/256, blk>>>(enc, ench, encl, BB*ENCC/4);
    tsplit_kernel<<<dim3(H3/32, EE/32),  blk>>>(k1,  k1h,  EE,   H3);
    split_kernel<<<(VV*EE/4 + 255)/256,   blk>>>(emb, embh, embl, VV*EE/4);

    {
        TJob a = {ench, encl, wi1h, nullptr, h1, h1h, h1l};
        TJob b = {ench, encl, wi2h, nullptr, h2, h2h, h2l};
        tc_gemm<<<dim3(HH/128, BB/128, 2), blk, SMEM_DYN>>>(a, b, a, ENCC, HH);
    }
    tsplit3_kernel<<<dim3(H3/32, HH/32, 3), blk>>>(rk1, rk1h, k2, k2h, rk2, rk2h);
    tsplit_kernel<<<dim3(VV/32, HH/32),  blk>>>(Wv,  wvh,  HH,   VV);
    {
        TJob a = {embh, embl, k1h, b1, proj, nullptr, nullptr};
        tc_gemm<<<dim3(H3/128, 1, 1), blk, SMEM_DYN>>>(a, a, a, EE, H3);
    }
    {
        TJob a = {h1h, h1l, rk1h, b1 + H3, in1, nullptr, nullptr};
        tc_gemm<<<dim3(H3/128, BB/128, 1), blk, SMEM_DYN>>>(a, a, a, HH, H3);
    }
    const int gblocks = BB * HH / 4 / 256;  // 1024
    gru_step1<<<gblocks, blk>>>(proj, tgt, 0, in1, h1, h1h, h1l);

    // ---- fork: sB joins the capture graph after the prologue ----
    cudaEventRecord(evFork, 0);
    cudaStreamWaitEvent(sB, evFork, 0);

    for (int t = 0; t < TT; t++) {
        if (t > 0) cudaStreamWaitEvent(0, evA, 0);

        // branch A (stream0): jobs 0+1 -> layer-2 gate update
        {
            TJob a = {h1h, h1l, k2h,  b2,      xg2, nullptr, nullptr};
            TJob b = {h2h, h2l, rk2h, b2 + H3, in2, nullptr, nullptr};
            tc_gemm<<<dim3(H3/128, BB/128, 2), blk, SMEM_DYN>>>(a, b, a, HH, H3);
        }
        cudaEventRecord(evB, 0);             // after L01: h1h reads complete
        gru_step2<<<gblocks, blk>>>(tgt, t, xg2, in2, h2, h2h, h2l, sqh, sql);

        // branch B (sB): job c -> layer-1 gate update for t+1
        if (t + 1 < TT) {
            TJob c = {h1h, h1l, rk1h, b1 + H3, in1, nullptr, nullptr};
            tc_gemm<<<dim3(H3/128, BB/128, 1), blk, SMEM_DYN, sB>>>(c, c, c, HH, H3);
            cudaStreamWaitEvent(sB, evB, 0); // gru1 writes h1h only after L01 read it
            gru_step1<<<gblocks, blk, 0, sB>>>(proj, tgt, t + 1, in1, h1, h1h, h1l);
            cudaEventRecord(evA, sB);
        }
    }

    // ---- join sB back into stream0 before epilogue ----
    cudaEventRecord(evJ, sB);
    cudaStreamWaitEvent(0, evJ, 0);

    // ---- logits = seq2 @ Wv + bv, then softmax (in d_out) ----
    {
        TJob a = {sqh, sql, wvh, bv, out, nullptr, nullptr};
        tc_gemm<<<dim3(VV/128, (BB*TT)/128, 1), blk, SMEM_DYN>>>(a, a, a, HH, VV);
    }
    softmax_kernel<<<(BB*TT)/8, blk>>>(out);
}

// round 15
// speedup vs baseline: 2.2008x; 1.4397x over previous
#include <cuda_runtime.h>
#include <cuda_fp16.h>
#include <stdint.h>
#include <math.h>

#define BB   2048
#define TT   48
#define HH   512
#define EE   256
#define VV   128
#define ENCC 1024
#define H3   1536

// ===================== stable-ISA PTX helpers (sm_80+) ======================
__device__ __forceinline__ uint32_t smem_u32(const void* p) {
    uint32_t a;
    asm("{ .reg .u64 t; cvta.to.shared.u64 t, %1; cvt.u32.u64 %0, t; }" : "=r"(a) : "l"(p));
    return a;
}
__device__ __forceinline__ void cp_async16(uint32_t dst, const void* src) {
    asm volatile("cp.async.cg.shared.global [%0], [%1], 16;" :: "r"(dst), "l"(src));
}
#define CP_COMMIT() asm volatile("cp.async.commit_group;" ::: "memory")
#define CP_WAIT1()  asm volatile("cp.async.wait_group 1;" ::: "memory")

__device__ __forceinline__ void ldsm_x4(uint32_t* r, uint32_t addr) {
    asm volatile("ldmatrix.sync.aligned.m8n8.x4.shared.b16 {%0,%1,%2,%3}, [%4];"
                 : "=r"(r[0]), "=r"(r[1]), "=r"(r[2]), "=r"(r[3]) : "r"(addr));
}
__device__ __forceinline__ void mma16816(float* d, const uint32_t* a, const uint32_t* b) {
    asm volatile("mma.sync.aligned.m16n8k16.row.col.f32.f16.f16.f32 "
                 "{%0,%1,%2,%3}, {%4,%5,%6,%7}, {%8,%9}, {%0,%1,%2,%3};"
                 : "+f"(d[0]), "+f"(d[1]), "+f"(d[2]), "+f"(d[3])
                 : "r"(a[0]), "r"(a[1]), "r"(a[2]), "r"(a[3]), "r"(b[0]), "r"(b[1]));
}

// ===================== device scratch (no allocations) ======================
__device__ __align__(16) float g_proj[VV * H3];
__device__ __align__(16) float g_h1 [BB * HH];
__device__ __align__(16) float g_h2 [BB * HH];
__device__ __align__(16) float g_in1[BB * H3];
__device__ __align__(16) float g_xg2[BB * H3];
__device__ __align__(16) float g_in2[BB * H3];

// activations: fp16 (A operands)
__device__ __align__(16) __half g_h1h[BB * HH];
__device__ __align__(16) __half g_h2h[BB * HH];
__device__ __align__(16) __half g_seqh[(size_t)BB * TT * HH];
__device__ __align__(16) __half g_ench[BB * ENCC];
__device__ __align__(16) __half g_embh[VV * EE];

// weights: fp16, transposed [N,K] (B operands)
__device__ __align__(16) __half g_k1h [H3 * EE];
__device__ __align__(16) __half g_rk1h[H3 * HH];
__device__ __align__(16) __half g_k2h [H3 * HH];
__device__ __align__(16) __half g_rk2h[H3 * HH];
__device__ __align__(16) __half g_wi1h[HH * ENCC];
__device__ __align__(16) __half g_wi2h[HH * ENCC];
__device__ __align__(16) __half g_wvh [VV * HH];

// ===================== prep: transpose / convert ============================
__global__ __launch_bounds__(256)
void tsplit_kernel(const float* __restrict__ W, __half* __restrict__ Th, int K, int N) {
    __shared__ float s[32][33];
    int n0 = blockIdx.x * 32, k0 = blockIdx.y * 32;
    int tx = threadIdx.x & 31, ty = threadIdx.x >> 5;
#pragma unroll
    for (int i = 0; i < 32; i += 8)
        s[ty + i][tx] = W[(size_t)(k0 + ty + i) * N + n0 + tx];
    __syncthreads();
#pragma unroll
    for (int i = 0; i < 32; i += 8)
        Th[(size_t)(n0 + ty + i) * K + k0 + tx] = __float2half(s[tx][ty + i]);
}

__global__ __launch_bounds__(256)
void tsplit3_kernel(const float* __restrict__ W0, __half* __restrict__ Th0,
                    const float* __restrict__ W1, __half* __restrict__ Th1,
                    const float* __restrict__ W2, __half* __restrict__ Th2) {
    const float* W = (blockIdx.z == 0) ? W0 : (blockIdx.z == 1) ? W1 : W2;
    __half* Th = (blockIdx.z == 0) ? Th0 : (blockIdx.z == 1) ? Th1 : Th2;
    const int K = HH, N = H3;
    __shared__ float s[32][33];
    int n0 = blockIdx.x * 32, k0 = blockIdx.y * 32;
    int tx = threadIdx.x & 31, ty = threadIdx.x >> 5;
#pragma unroll
    for (int i = 0; i < 32; i += 8)
        s[ty + i][tx] = W[(size_t)(k0 + ty + i) * N + n0 + tx];
    __syncthreads();
#pragma unroll
    for (int i = 0; i < 32; i += 8)
        Th[(size_t)(n0 + ty + i) * K + k0 + tx] = __float2half(s[tx][ty + i]);
}

__global__ __launch_bounds__(256)
void split_kernel(const float* __restrict__ src, __half* __restrict__ dh, int n4) {
    int i = blockIdx.x * 256 + threadIdx.x;
    if (i >= n4) return;
    float4 v = ((const float4*)src)[i];
    ((__half2*)dh)[2*i]   = __halves2half2(__float2half(v.x), __float2half(v.y));
    ((__half2*)dh)[2*i+1] = __halves2half2(__float2half(v.z), __float2half(v.w));
}

// ===================== mma.sync single-pass fp16 GEMM =======================
// C = Ah @ Bh^T, fp32 accumulate. 3-stage cp.async pipeline, XOR swizzle,
// one __syncthreads per K-chunk.
#define TILE_B    (128 * 32 * 2)         // 8192 bytes per operand tile
#define STAGE_B   (2 * TILE_B)           // A, B = 16384
#define SMEM_DYN  (3 * STAGE_B)          // 49152 bytes

#define SWOFF(r, u) ((r) * 64 + (((u) ^ (((r) >> 1) & 3)) * 16))

struct TJob {
    const __half *Ah;        // [M,K]
    const __half *Bh;        // [N,K]
    const float* bias;
    float* C;
    __half *Ch;              // optional fp16 copy of C
};

__global__ __launch_bounds__(256, 2)
void tc_gemm(TJob j0, TJob j1, TJob j2, int K, int N) {
    extern __shared__ __align__(16) char smem[];
    const TJob& jb = (blockIdx.z == 0) ? j0 : (blockIdx.z == 1) ? j1 : j2;
    const uint32_t sb = smem_u32(smem);
    const int tid = threadIdx.x;
    const int lane = tid & 31, warp = tid >> 5;
    const int wm = warp & 1, wn = warp >> 1;
    const int bm = blockIdx.y * 128, bn = blockIdx.x * 128;
    const int kch = K / 32;

    auto issue = [&](int c) {
        const int k0 = c * 32;
        const uint32_t st = sb + (c % 3) * STAGE_B;
#pragma unroll
        for (int i = 0; i < 4; i++) {
            const int tile = i >> 1;
            const int w = (i & 1) ? (tid + 256) & 511 : tid;
            const int row = w >> 2, u = w & 3;
            const __half* src = (tile == 0) ? jb.Ah : jb.Bh;
            const int roff = (tile == 0) ? bm : bn;
            cp_async16(st + tile * TILE_B + SWOFF(row, u),
                       src + (size_t)(roff + row) * K + k0 + u * 8);
        }
    };

    float acc[4][4][4];
#pragma unroll
    for (int i = 0; i < 4; i++)
#pragma unroll
        for (int j = 0; j < 4; j++)
#pragma unroll
            for (int q = 0; q < 4; q++) acc[i][j][q] = 0.f;

    const int arow = lane & 15, au = (lane >> 4);
    const int brow4 = lane & 7;
    const int bu = (lane >> 3) & 1;
    const int bnsel = ((lane >> 4) & 1) * 8;

    issue(0); CP_COMMIT();
    issue(1); CP_COMMIT();

    for (int c = 0; c < kch; c++) {
        CP_WAIT1();
        __syncthreads();
        if (c + 2 < kch) issue(c + 2);
        CP_COMMIT();

        const uint32_t st = sb + (c % 3) * STAGE_B;
        const uint32_t ah = st, bh = st + TILE_B;
#pragma unroll
        for (int kt = 0; kt < 2; kt++) {
            uint32_t afh[4][4], bfh[2][4];
#pragma unroll
            for (int mt = 0; mt < 4; mt++) {
                int r = wm * 64 + mt * 16 + arow;
                ldsm_x4(afh[mt], ah + SWOFF(r, kt * 2 + au));
            }
#pragma unroll
            for (int p = 0; p < 2; p++) {
                int r = wn * 32 + p * 16 + bnsel + brow4;
                ldsm_x4(bfh[p], bh + SWOFF(r, kt * 2 + bu));
            }
#pragma unroll
            for (int mt = 0; mt < 4; mt++)
#pragma unroll
                for (int nt = 0; nt < 4; nt++)
                    mma16816(acc[mt][nt], afh[mt], &bfh[nt >> 1][(nt & 1) * 2]);
        }
    }

    const int quad = lane >> 2, pair = lane & 3;
#pragma unroll
    for (int mt = 0; mt < 4; mt++) {
#pragma unroll
        for (int h = 0; h < 2; h++) {
            int row = bm + wm * 64 + mt * 16 + quad + h * 8;
            float* crow = jb.C + (size_t)row * N;
#pragma unroll
            for (int nt = 0; nt < 4; nt++) {
                int col = bn + wn * 32 + nt * 8 + pair * 2;
                float v0 = acc[mt][nt][2 * h]     + (jb.bias ? jb.bias[col]     : 0.f);
                float v1 = acc[mt][nt][2 * h + 1] + (jb.bias ? jb.bias[col + 1] : 0.f);
                *(float2*)(crow + col) = make_float2(v0, v1);
                if (jb.Ch)
                    *(__half2*)(jb.Ch + (size_t)row * N + col) =
                        __halves2half2(__float2half(v0), __float2half(v1));
            }
        }
    }
}

// ===================== GRU gate updates =====================================
__device__ __forceinline__ float sigm_(float x) { return 1.f / (1.f + expf(-x)); }

__device__ __forceinline__ void gate4(const float4& xz, const float4& xr, const float4& xh,
                                      const float4& rz, const float4& rr, const float4& rh,
                                      float4& hv) {
    float z, r, hg;
    z = sigm_(xz.x + rz.x); r = sigm_(xr.x + rr.x); hg = tanhf(xh.x + r * rh.x); hv.x = z * hv.x + (1.f - z) * hg;
    z = sigm_(xz.y + rz.y); r = sigm_(xr.y + rr.y); hg = tanhf(xh.y + r * rh.y); hv.y = z * hv.y + (1.f - z) * hg;
    z = sigm_(xz.z + rz.z); r = sigm_(xr.z + rr.z); hg = tanhf(xh.z + r * rh.z); hv.z = z * hv.z + (1.f - z) * hg;
    z = sigm_(xz.w + rz.w); r = sigm_(xr.w + rr.w); hg = tanhf(xh.w + r * rh.w); hv.w = z * hv.w + (1.f - z) * hg;
}
__device__ __forceinline__ void store_h4(const float4& hv, __half* ph) {
    *(__half2*)(ph)     = __halves2half2(__float2half(hv.x), __float2half(hv.y));
    *(__half2*)(ph + 2) = __halves2half2(__float2half(hv.z), __float2half(hv.w));
}

// layer-1 update at time t1
__global__ __launch_bounds__(256)
void gru_step1(const float* __restrict__ proj, const int* __restrict__ tgt, int t1,
               const float* __restrict__ in1, float* __restrict__ h1,
               __half* __restrict__ h1h) {
    int idx = blockIdx.x * 256 + threadIdx.x;
    int b = idx >> 7;
    int j = (idx & 127) * 4;
    size_t hidx = (size_t)b * HH + j;
    int tok = tgt[b * TT + t1];
    if (tok != 0) {
        float4 hv = *(float4*)(h1 + hidx);
        const float* xg = proj + (size_t)tok * H3;
        const float* in = in1 + (size_t)b * H3;
        gate4(*(const float4*)(xg + j), *(const float4*)(xg + HH + j), *(const float4*)(xg + 2*HH + j),
              *(const float4*)(in + j), *(const float4*)(in + HH + j), *(const float4*)(in + 2*HH + j), hv);
        *(float4*)(h1 + hidx) = hv;
        store_h4(hv, h1h + hidx);
    }
}

// layer-2 update at time t2 + seq emit
__global__ __launch_bounds__(256)
void gru_step2(const int* __restrict__ tgt, int t2,
               const float* __restrict__ xg2, const float* __restrict__ in2,
               float* __restrict__ h2,
               __half* __restrict__ h2h, __half* __restrict__ seqh) {
    int idx = blockIdx.x * 256 + threadIdx.x;
    int b = idx >> 7;
    int j = (idx & 127) * 4;
    size_t hidx = (size_t)b * HH + j;

    float4 hv = *(float4*)(h2 + hidx);
    if (tgt[b * TT + t2] != 0) {
        const float* xg = xg2 + (size_t)b * H3;
        const float* in = in2 + (size_t)b * H3;
        gate4(*(const float4*)(xg + j), *(const float4*)(xg + HH + j), *(const float4*)(xg + 2*HH + j),
              *(const float4*)(in + j), *(const float4*)(in + HH + j), *(const float4*)(in + 2*HH + j), hv);
        *(float4*)(h2 + hidx) = hv;
        store_h4(hv, h2h + hidx);
    }
    size_t so = (size_t)b * (TT * HH) + (size_t)t2 * HH + j;
    store_h4(hv, seqh + so);   // output == state, even masked
}

// ===================== softmax over V=128 ===================================
__global__ __launch_bounds__(256)
void softmax_kernel(float* __restrict__ out) {
    int row  = blockIdx.x * 8 + (threadIdx.x >> 5);
    int lane = threadIdx.x & 31;
    float* p = out + (size_t)row * VV + lane * 4;
    float4 v = *(float4*)p;
    float m = fmaxf(fmaxf(v.x, v.y), fmaxf(v.z, v.w));
#pragma unroll
    for (int o = 16; o > 0; o >>= 1) m = fmaxf(m, __shfl_xor_sync(0xffffffffu, m, o));
    v.x = expf(v.x - m); v.y = expf(v.y - m); v.z = expf(v.z - m); v.w = expf(v.w - m);
    float s = v.x + v.y + v.z + v.w;
#pragma unroll
    for (int o = 16; o > 0; o >>= 1) s += __shfl_xor_sync(0xffffffffu, s, o);
    float inv = 1.f / s;
    v.x *= inv; v.y *= inv; v.z *= inv; v.w *= inv;
    *(float4*)p = v;
}

// ===================== launch ===============================================
static void* sym(const void* s) { void* p; cudaGetSymbolAddress(&p, s); return p; }

extern "C" void kernel_launch(void* const* d_in, const int* in_sizes, int n_in,
                              void* d_out, int out_size) {
    const int*   tgt = (const int*)  d_in[0];
    const float* enc = (const float*)d_in[1];
    const float* Wi1 = (const float*)d_in[2];
    const float* Wi2 = (const float*)d_in[3];
    const float* emb = (const float*)d_in[4];
    const float* k1  = (const float*)d_in[5];
    const float* rk1 = (const float*)d_in[6];
    const float* b1  = (const float*)d_in[7];
    const float* k2  = (const float*)d_in[8];
    const float* rk2 = (const float*)d_in[9];
    const float* b2  = (const float*)d_in[10];
    const float* Wv  = (const float*)d_in[11];
    const float* bv  = (const float*)d_in[12];
    float* out = (float*)d_out;

    float* proj = (float*)sym(g_proj);
    float* h1  = (float*)sym(g_h1);   float* h2  = (float*)sym(g_h2);
    float* in1 = (float*)sym(g_in1);  float* xg2 = (float*)sym(g_xg2);  float* in2 = (float*)sym(g_in2);
    __half *h1h=(__half*)sym(g_h1h);
    __half *h2h=(__half*)sym(g_h2h);
    __half *sqh=(__half*)sym(g_seqh);
    __half *ench=(__half*)sym(g_ench);
    __half *embh=(__half*)sym(g_embh);
    __half *k1h=(__half*)sym(g_k1h);
    __half *rk1h=(__half*)sym(g_rk1h);
    __half *k2h=(__half*)sym(g_k2h);
    __half *rk2h=(__half*)sym(g_rk2h);
    __half *wi1h=(__half*)sym(g_wi1h);
    __half *wi2h=(__half*)sym(g_wi2h);
    __half *wvh=(__half*)sym(g_wvh);

    cudaFuncSetAttribute(tc_gemm, cudaFuncAttributeMaxDynamicSharedMemorySize, SMEM_DYN);

    // side stream + events for fork-join capture (created per call; leaked)
    cudaStream_t sB;
    cudaStreamCreateWithFlags(&sB, cudaStreamNonBlocking);
    cudaEvent_t evFork, evA, evB, evJ;
    cudaEventCreateWithFlags(&evFork, cudaEventDisableTiming);
    cudaEventCreateWithFlags(&evA,    cudaEventDisableTiming);
    cudaEventCreateWithFlags(&evB,    cudaEventDisableTiming);
    cudaEventCreateWithFlags(&evJ,    cudaEventDisableTiming);

    dim3 blk(256);

    // ---- prep (stream 0) ----
    tsplit_kernel<<<dim3(HH/32, ENCC/32),blk>>>(Wi1, wi1h, ENCC, HH);
    tsplit_kernel<<<dim3(HH/32, ENCC/32),blk>>>(Wi2, wi2h, ENCC, HH);
    split_kernel<<<(BB*ENCC/4 + 255)/256, blk>>>(enc, ench, BB*ENCC/4);
    tsplit_kernel<<<dim3(H3/32, EE/32),  blk>>>(k1,  k1h,  EE,   H3);
    split_kernel<<<(VV*EE/4 + 255)/256,   blk>>>(emb, embh, VV*EE/4);

    {
        TJob a = {ench, wi1h, nullptr, h1, h1h};
        TJob b = {ench, wi2h, nullptr, h2, h2h};
        tc_gemm<<<dim3(HH/128, BB/128, 2), blk, SMEM_DYN>>>(a, b, a, ENCC, HH);
    }
    tsplit3_kernel<<<dim3(H3/32, HH/32, 3), blk>>>(rk1, rk1h, k2, k2h, rk2, rk2h);
    tsplit_kernel<<<dim3(VV/32, HH/32),  blk>>>(Wv,  wvh,  HH,   VV);
    {
        TJob a = {embh, k1h, b1, proj, nullptr};
        tc_gemm<<<dim3(H3/128, 1, 1), blk, SMEM_DYN>>>(a, a, a, EE, H3);
    }
    {
        TJob a = {h1h, rk1h, b1 + H3, in1, nullptr};
        tc_gemm<<<dim3(H3/128, BB/128, 1), blk, SMEM_DYN>>>(a, a, a, HH, H3);
    }
    const int gblocks = BB * HH / 4 / 256;  // 1024
    gru_step1<<<gblocks, blk>>>(proj, tgt, 0, in1, h1, h1h);

    // ---- fork: sB joins the capture graph after the prologue ----
    cudaEventRecord(evFork, 0);
    cudaStreamWaitEvent(sB, evFork, 0);

    for (int t = 0; t < TT; t++) {
        if (t > 0) cudaStreamWaitEvent(0, evA, 0);

        // branch A (stream0): jobs 0+1 -> layer-2 gate update
        {
            TJob a = {h1h, k2h,  b2,      xg2, nullptr};
            TJob b = {h2h, rk2h, b2 + H3, in2, nullptr};
            tc_gemm<<<dim3(H3/128, BB/128, 2), blk, SMEM_DYN>>>(a, b, a, HH, H3);
        }
        cudaEventRecord(evB, 0);             // after L01: h1h reads complete
        gru_step2<<<gblocks, blk>>>(tgt, t, xg2, in2, h2, h2h, sqh);

        // branch B (sB): job c -> layer-1 gate update for t+1
        if (t + 1 < TT) {
            TJob c = {h1h, rk1h, b1 + H3, in1, nullptr};
            tc_gemm<<<dim3(H3/128, BB/128, 1), blk, SMEM_DYN, sB>>>(c, c, c, HH, H3);
            cudaStreamWaitEvent(sB, evB, 0); // gru1 writes h1h only after L01 read it
            gru_step1<<<gblocks, blk, 0, sB>>>(proj, tgt, t + 1, in1, h1, h1h);
            cudaEventRecord(evA, sB);
        }
    }

    // ---- join sB back into stream0 before epilogue ----
    cudaEventRecord(evJ, sB);
    cudaStreamWaitEvent(0, evJ, 0);

    // ---- logits = seq2 @ Wv + bv, then softmax (in d_out) ----
    {
        TJob a = {sqh, wvh, bv, out, nullptr};
        tc_gemm<<<dim3(VV/128, (BB*TT)/128, 1), blk, SMEM_DYN>>>(a, a, a, HH, VV);
    }
    softmax_kernel<<<(BB*TT)/8, blk>>>(out);
}